// round 9
// baseline (speedup 1.0000x reference)
#include <cuda_runtime.h>
#include <math.h>
#include <stdint.h>

#define Bq 512
#define Wq 40
#define Vq 12000
#define Eq 512
#define Hq 512
#define G4 2048   // 4*H
#define NCTA 128

// ---------------- scratch (device globals; no allocation) ----------------
__device__ float g_table[(size_t)Vq * Eq];        // rounded tanh(lut^T)
__device__ float g_emb[Bq * Wq * Eq];
__device__ float g_xg[2 * (size_t)Bq * Wq * G4];  // per-dir input projections
__device__ float g_hseq[Bq * Wq * 2 * Hq];        // layer output sequence
__device__ float g_ha[2][2 * Bq * Hq];            // h ping-pong (GEMM A, rounded)
__device__ float g_c[2 * Bq * Hq];
__device__ float g_wr[10485760];                  // rounded weights: wih0|whh0|wih1|whh1
__device__ unsigned g_bar[2 * Wq];

#define OFF_WIH0 0
#define OFF_WHH0 2097152
#define OFF_WIH1 4194304
#define OFF_WHH1 8388608

__device__ __forceinline__ float sig_fast(float x) {
    return __fdividef(1.0f, 1.0f + __expf(-x));
}
__device__ __forceinline__ float tanh_fast(float x) {
    return 2.0f * __fdividef(1.0f, 1.0f + __expf(-2.0f * x)) - 1.0f;
}
// RNA-round fp32 to tf32-compatible fp32 (low 13 mantissa bits zero)
__device__ __forceinline__ float rnd_tf32(float x) {
    uint32_t r;
    asm("cvt.rna.tf32.f32 %0, %1;" : "=r"(r) : "f"(x));
    return __uint_as_float(r);
}
__device__ __forceinline__ void cp16(uint32_t dst, const void* src) {
    asm volatile("cp.async.cg.shared.global [%0], [%1], 16;" :: "r"(dst), "l"(src));
}

__global__ void zero_bar_kernel() {
    if (threadIdx.x < 2 * Wq) g_bar[threadIdx.x] = 0;
}

// ---------------- one-time weight pre-round ----------------
__global__ void round_weights_kernel(const float* __restrict__ src, int dstOff, int n) {
    int i = blockIdx.x * blockDim.x + threadIdx.x;
    if (i < n) g_wr[dstOff + i] = rnd_tf32(src[i]);
}

// ---------------- tanh + transpose lookup: g_table[v][e] = rnd(tanh(lut[e][v])) --
__global__ void tanh_transpose_kernel(const float* __restrict__ lut) {
    __shared__ float tile[32][33];
    int v0 = blockIdx.x * 32;
    int e0 = blockIdx.y * 32;
    int tx = threadIdx.x, ty = threadIdx.y;
#pragma unroll
    for (int i = ty; i < 32; i += 8) {
        int e = e0 + i, v = v0 + tx;
        tile[i][tx] = (v < Vq) ? lut[(size_t)e * Vq + v] : 0.0f;
    }
    __syncthreads();
#pragma unroll
    for (int i = ty; i < 32; i += 8) {
        int v = v0 + i, e = e0 + tx;
        if (v < Vq) g_table[(size_t)v * Eq + e] = rnd_tf32(tanhf(tile[tx][i]));
    }
}

// ---------------- embedding gather ----------------
__global__ void embed_kernel(const int* __restrict__ ques) {
    int idx = blockIdx.x * blockDim.x + threadIdx.x;
    if (idx >= Bq * Wq * Eq) return;
    int e = idx & (Eq - 1);
    int bw = idx >> 9;
    int v = ques[bw];
    g_emb[idx] = (v > 0) ? g_table[(size_t)(v - 1) * Eq + e] : 0.0f;
}

// ---------------- TF32 tensor-core NT GEMM, 4-stage cp.async, 1 sync/iter ------
// Operands pre-rounded to tf32 grid; smem holds raw bits, mma reads top 19.
#define P_ASZ (128 * 20)
#define P_SMEM (4 * P_ASZ * 2 * 4)  // 81920 B
template <int HAS_BIAS>
__global__ __launch_bounds__(256, 2) void gemm_tf32(
    const float* __restrict__ A, size_t aDirStride,
    const float* __restrict__ Bw, size_t bDirStride,
    const float* __restrict__ bias,
    float* __restrict__ C, size_t cDirStride,
    int M, int N, int K)
{
    extern __shared__ uint32_t sm[];
    uint32_t* smA = sm;                 // [4][128][20]
    uint32_t* smB = sm + 4 * P_ASZ;
    uint32_t baseA = (uint32_t)__cvta_generic_to_shared(smA);
    uint32_t baseB = (uint32_t)__cvta_generic_to_shared(smB);

    int dir = blockIdx.z;
    A  += (size_t)dir * aDirStride;
    Bw += (size_t)dir * bDirStride;
    C  += (size_t)dir * cDirStride;

    int m0 = blockIdx.y * 128;
    int n0 = blockIdx.x * 128;
    int tid = threadIdx.x;
    int wid = tid >> 5, lane = tid & 31;
    int wm = wid >> 2, wn = wid & 3;
    int gid = lane >> 2, tg = lane & 3;

    float acc[4][4][4];
#pragma unroll
    for (int mt = 0; mt < 4; mt++)
#pragma unroll
        for (int nt = 0; nt < 4; nt++)
#pragma unroll
            for (int r = 0; r < 4; r++) acc[mt][nt][r] = 0.0f;

    int niter = K >> 4;

    auto load_stage = [&](int s, int k0) {
#pragma unroll
        for (int i = 0; i < 2; i++) {
            int c = tid + i * 256;
            int row = c >> 2, seg = c & 3;
            cp16(baseA + (s * P_ASZ + row * 20 + seg * 4) * 4,
                 A + (size_t)(m0 + row) * K + k0 + seg * 4);
            cp16(baseB + (s * P_ASZ + row * 20 + seg * 4) * 4,
                 Bw + (size_t)(n0 + row) * K + k0 + seg * 4);
        }
        asm volatile("cp.async.commit_group;");
    };

    load_stage(0, 0);
    load_stage(1, 16);
    load_stage(2, 32);

    for (int it = 0; it < niter; it++) {
        int rem = niter - 1 - it;
        if (rem >= 2)      asm volatile("cp.async.wait_group 2;");
        else if (rem == 1) asm volatile("cp.async.wait_group 1;");
        else               asm volatile("cp.async.wait_group 0;");
        __syncthreads();
        if (it + 3 < niter) load_stage((it + 3) & 3, (it + 3) * 16);

        const uint32_t* Asb = smA + (it & 3) * P_ASZ;
        const uint32_t* Bsb = smB + (it & 3) * P_ASZ;
#pragma unroll
        for (int kk = 0; kk < 16; kk += 8) {
            uint32_t af[4][4], bf[4][2];
#pragma unroll
            for (int mt = 0; mt < 4; mt++) {
                int m = wm * 64 + mt * 16 + gid;
                af[mt][0] = Asb[m * 20 + kk + tg];
                af[mt][1] = Asb[(m + 8) * 20 + kk + tg];
                af[mt][2] = Asb[m * 20 + kk + tg + 4];
                af[mt][3] = Asb[(m + 8) * 20 + kk + tg + 4];
            }
#pragma unroll
            for (int nt = 0; nt < 4; nt++) {
                int n = wn * 32 + nt * 8 + gid;
                bf[nt][0] = Bsb[n * 20 + kk + tg];
                bf[nt][1] = Bsb[n * 20 + kk + tg + 4];
            }
#pragma unroll
            for (int mt = 0; mt < 4; mt++)
#pragma unroll
                for (int nt = 0; nt < 4; nt++) {
                    asm volatile(
                        "mma.sync.aligned.m16n8k8.row.col.f32.tf32.tf32.f32 "
                        "{%0,%1,%2,%3}, {%4,%5,%6,%7}, {%8,%9}, {%0,%1,%2,%3};"
                        : "+f"(acc[mt][nt][0]), "+f"(acc[mt][nt][1]),
                          "+f"(acc[mt][nt][2]), "+f"(acc[mt][nt][3])
                        : "r"(af[mt][0]), "r"(af[mt][1]), "r"(af[mt][2]), "r"(af[mt][3]),
                          "r"(bf[nt][0]), "r"(bf[nt][1]));
                }
        }
    }

    const float* bp = bias + (size_t)dir * 2 * G4;
#pragma unroll
    for (int mt = 0; mt < 4; mt++) {
#pragma unroll
        for (int nt = 0; nt < 4; nt++) {
            int m = m0 + wm * 64 + mt * 16 + gid;
            int n = n0 + wn * 32 + nt * 8 + tg * 2;
            float2 v0, v1;
            v0.x = acc[mt][nt][0]; v0.y = acc[mt][nt][1];
            v1.x = acc[mt][nt][2]; v1.y = acc[mt][nt][3];
            if (HAS_BIAS) {
                float bx = bp[n] + bp[G4 + n];
                float by = bp[n + 1] + bp[G4 + n + 1];
                v0.x += bx; v0.y += by; v1.x += bx; v1.y += by;
            }
            *(float2*)(C + (size_t)m * N + n) = v0;
            *(float2*)(C + (size_t)(m + 8) * N + n) = v1;
        }
    }
}

// ---------------- persistent fused LSTM recurrence (one layer, both dirs) -------
// 4-stage cp.async, 1 sync per chunk. ROUND_HSEQ as before.
#define R_ASZ (64 * 36)
#define R_BSZ (256 * 36)
#define R_SMEM (4 * (R_ASZ + R_BSZ) * 4)   // 184320 B
#define GSM_STRIDE 258
template <int ROUND_HSEQ>
__global__ __launch_bounds__(256) void lstm_persist(
    const float* __restrict__ whh,       // [2 dirs][G4][Hq] pre-rounded
    const float* __restrict__ xg,        // [2 dirs][Bq][Wq][G4]
    int bar_ofs)
{
    extern __shared__ uint32_t sm[];
    uint32_t* smA = sm;                   // [4][64][36]
    uint32_t* smB = sm + 4 * R_ASZ;       // [4][256][36]
    float* gsm = (float*)sm;              // epilogue alias [64][258]
    uint32_t baseA = (uint32_t)__cvta_generic_to_shared(smA);
    uint32_t baseB = (uint32_t)__cvta_generic_to_shared(smB);

    int tid = threadIdx.x;
    int bx = blockIdx.x;
    int dir = bx >> 6;
    int r = bx & 63;
    int m0 = (r >> 3) * 64;
    int ht0 = (r & 7) * 64;

    int wid = tid >> 5, lane = tid & 31;
    int wm = wid >> 2, wn = wid & 3;      // warp tile: 32 m x 64 n
    int gid = lane >> 2, tg = lane & 3;

    const float* wbase = whh + (size_t)dir * G4 * Hq;
    const float* xgd = xg + (size_t)dir * Bq * Wq * G4;

    for (int step = 0; step < Wq; step++) {
        float acc[2][8][4];
#pragma unroll
        for (int mt = 0; mt < 2; mt++)
#pragma unroll
            for (int t = 0; t < 8; t++)
#pragma unroll
                for (int q = 0; q < 4; q++) acc[mt][t][q] = 0.0f;

        if (step > 0) {
            const float* habase = g_ha[(step - 1) & 1] + dir * Bq * Hq;

            auto load_stage = [&](int s, int k0) {
#pragma unroll
                for (int i = 0; i < 2; i++) {
                    int c = tid + i * 256;
                    int row = c >> 3, seg = c & 7;
                    cp16(baseA + (s * R_ASZ + row * 36 + seg * 4) * 4,
                         habase + (size_t)(m0 + row) * Hq + k0 + seg * 4);
                }
#pragma unroll
                for (int i = 0; i < 8; i++) {
                    int c = tid + i * 256;
                    int row = c >> 3, seg = c & 7;
                    int grow = ((row >> 6) << 9) + ht0 + (row & 63);
                    cp16(baseB + (s * R_BSZ + row * 36 + seg * 4) * 4,
                         wbase + (size_t)grow * Hq + k0 + seg * 4);
                }
                asm volatile("cp.async.commit_group;");
            };

            load_stage(0, 0);
            load_stage(1, 32);
            load_stage(2, 64);

            for (int kc = 0; kc < 16; kc++) {
                int rem = 15 - kc;
                if (rem >= 2)      asm volatile("cp.async.wait_group 2;");
                else if (rem == 1) asm volatile("cp.async.wait_group 1;");
                else               asm volatile("cp.async.wait_group 0;");
                __syncthreads();
                if (kc + 3 < 16) load_stage((kc + 3) & 3, (kc + 3) * 32);

                const uint32_t* Asb = smA + (kc & 3) * R_ASZ;
                const uint32_t* Bsb = smB + (kc & 3) * R_BSZ;
#pragma unroll
                for (int kk = 0; kk < 32; kk += 8) {
                    uint32_t af[2][4], bf[8][2];
#pragma unroll
                    for (int mt = 0; mt < 2; mt++) {
                        int mr = wm * 32 + mt * 16 + gid;
                        af[mt][0] = Asb[mr * 36 + kk + tg];
                        af[mt][1] = Asb[(mr + 8) * 36 + kk + tg];
                        af[mt][2] = Asb[mr * 36 + kk + tg + 4];
                        af[mt][3] = Asb[(mr + 8) * 36 + kk + tg + 4];
                    }
#pragma unroll
                    for (int t = 0; t < 8; t++) {
                        int br = ((t >> 1) << 6) + wn * 16 + ((t & 1) << 3) + gid;
                        bf[t][0] = Bsb[br * 36 + kk + tg];
                        bf[t][1] = Bsb[br * 36 + kk + tg + 4];
                    }
#pragma unroll
                    for (int mt = 0; mt < 2; mt++)
#pragma unroll
                        for (int t = 0; t < 8; t++) {
                            asm volatile(
                                "mma.sync.aligned.m16n8k8.row.col.f32.tf32.tf32.f32 "
                                "{%0,%1,%2,%3}, {%4,%5,%6,%7}, {%8,%9}, {%0,%1,%2,%3};"
                                : "+f"(acc[mt][t][0]), "+f"(acc[mt][t][1]),
                                  "+f"(acc[mt][t][2]), "+f"(acc[mt][t][3])
                                : "r"(af[mt][0]), "r"(af[mt][1]), "r"(af[mt][2]), "r"(af[mt][3]),
                                  "r"(bf[t][0]), "r"(bf[t][1]));
                        }
                }
            }
        }

        // ---- stage gates into smem (reuses pipeline buffers) ----
        __syncthreads();
#pragma unroll
        for (int mt = 0; mt < 2; mt++)
#pragma unroll
            for (int t = 0; t < 8; t++)
#pragma unroll
                for (int rs = 0; rs < 2; rs++) {
                    int mr = wm * 32 + mt * 16 + gid + rs * 8;
                    int nc = ((t >> 1) << 6) + wn * 16 + ((t & 1) << 3) + tg * 2;
                    float2 v;
                    v.x = acc[mt][t][rs * 2];
                    v.y = acc[mt][t][rs * 2 + 1];
                    *(float2*)&gsm[mr * GSM_STRIDE + nc] = v;
                }
        __syncthreads();

        // ---- coalesced fused gate epilogue ----
        int t_ = dir ? (Wq - 1 - step) : step;
        float* haw = g_ha[step & 1] + dir * Bq * Hq;
        int hl = (tid & 31) * 2;
        int mb = tid >> 5;
#pragma unroll
        for (int mm = 0; mm < 8; mm++) {
            int m = mb + mm * 8;
            int gm = m0 + m;
            const float* gr = &gsm[m * GSM_STRIDE];
            const float* xp = xgd + ((size_t)gm * Wq + t_) * G4 + ht0 + hl;
            float2 gi = *(const float2*)&gr[hl];
            float2 gf = *(const float2*)&gr[64 + hl];
            float2 gg = *(const float2*)&gr[128 + hl];
            float2 go = *(const float2*)&gr[192 + hl];
            float2 xi = *(const float2*)&xp[0];
            float2 xf = *(const float2*)&xp[512];
            float2 xgg = *(const float2*)&xp[1024];
            float2 xo = *(const float2*)&xp[1536];
            int ci = dir * Bq * Hq + gm * Hq + ht0 + hl;
            float2 cprev = (step == 0) ? make_float2(0.f, 0.f) : *(const float2*)&g_c[ci];
            float2 cv, hv;
            cv.x = sig_fast(gf.x + xf.x) * cprev.x + sig_fast(gi.x + xi.x) * tanh_fast(gg.x + xgg.x);
            cv.y = sig_fast(gf.y + xf.y) * cprev.y + sig_fast(gi.y + xi.y) * tanh_fast(gg.y + xgg.y);
            hv.x = sig_fast(go.x + xo.x) * tanh_fast(cv.x);
            hv.y = sig_fast(go.y + xo.y) * tanh_fast(cv.y);
            *(float2*)&g_c[ci] = cv;
            float2 hr;
            hr.x = rnd_tf32(hv.x);
            hr.y = rnd_tf32(hv.y);
            *(float2*)&haw[gm * Hq + ht0 + hl] = hr;
            float2 hs = ROUND_HSEQ ? hr : hv;
            *(float2*)&g_hseq[((size_t)gm * Wq + t_) * (2 * Hq) + dir * Hq + ht0 + hl] = hs;
        }

        // ---- grid barrier ----
        if (step < Wq - 1) {
            __threadfence();
            __syncthreads();
            if (tid == 0) {
                unsigned* ctr = &g_bar[bar_ofs + step];
                atomicAdd(ctr, 1u);
                unsigned v;
                do {
                    asm volatile("ld.acquire.gpu.u32 %0, [%1];"
                                 : "=r"(v) : "l"(ctr) : "memory");
                    if (v < NCTA) __nanosleep(64);
                } while (v < NCTA);
            }
            __syncthreads();
        }
    }
}

// ---------------- final gather at t = len-1 ----------------
__global__ void gather_kernel(const int* __restrict__ qlen, float* __restrict__ out) {
    int idx = blockIdx.x * blockDim.x + threadIdx.x;
    if (idx >= Bq * 2 * Hq) return;
    int b = idx / (2 * Hq);
    int j = idx - b * (2 * Hq);
    int t = qlen[b] - 1;
    out[idx] = g_hseq[((size_t)b * Wq + t) * (2 * Hq) + j];
}

// ---------------- launch ----------------
extern "C" void kernel_launch(void* const* d_in, const int* in_sizes, int n_in,
                              void* d_out, int out_size)
{
    const int*   ques = (const int*)d_in[0];
    const int*   qlen = (const int*)d_in[1];
    const float* lut  = (const float*)d_in[2];
    const float* wih0 = (const float*)d_in[3];
    const float* whh0 = (const float*)d_in[4];
    const float* b0   = (const float*)d_in[5];
    const float* wih1 = (const float*)d_in[6];
    const float* whh1 = (const float*)d_in[7];
    const float* b1   = (const float*)d_in[8];
    float* out = (float*)d_out;

    float *emb, *xg, *hseq, *wr;
    cudaGetSymbolAddress((void**)&emb,  g_emb);
    cudaGetSymbolAddress((void**)&xg,   g_xg);
    cudaGetSymbolAddress((void**)&hseq, g_hseq);
    cudaGetSymbolAddress((void**)&wr,   g_wr);

    cudaFuncSetAttribute(gemm_tf32<1>, cudaFuncAttributeMaxDynamicSharedMemorySize, P_SMEM);
    cudaFuncSetAttribute(lstm_persist<0>, cudaFuncAttributeMaxDynamicSharedMemorySize, R_SMEM);
    cudaFuncSetAttribute(lstm_persist<1>, cudaFuncAttributeMaxDynamicSharedMemorySize, R_SMEM);

    // 0) barriers + pre-rounded weights + table
    zero_bar_kernel<<<1, 128>>>();
    round_weights_kernel<<<(2097152 + 255) / 256, 256>>>(wih0, OFF_WIH0, 2097152);
    round_weights_kernel<<<(2097152 + 255) / 256, 256>>>(whh0, OFF_WHH0, 2097152);
    round_weights_kernel<<<(4194304 + 255) / 256, 256>>>(wih1, OFF_WIH1, 4194304);
    round_weights_kernel<<<(2097152 + 255) / 256, 256>>>(whh1, OFF_WHH1, 2097152);
    {
        dim3 grid((Vq + 31) / 32, Eq / 32);
        tanh_transpose_kernel<<<grid, dim3(32, 8)>>>(lut);
    }

    // 1) embedding
    embed_kernel<<<(Bq * Wq * Eq + 255) / 256, 256>>>(ques);

    // 2) layer-0 input projection
    {
        dim3 grid(G4 / 128, (Bq * Wq) / 128, 2);
        gemm_tf32<1><<<grid, 256, P_SMEM>>>(emb, 0,
                                            wr + OFF_WIH0, (size_t)G4 * Eq,
                                            b0,
                                            xg, (size_t)Bq * Wq * G4,
                                            Bq * Wq, G4, Eq);
    }

    // 3) layer-0 recurrence (hseq rounded -> feeds layer-1 GEMM)
    lstm_persist<1><<<NCTA, 256, R_SMEM>>>(wr + OFF_WHH0, xg, 0);

    // 4) layer-1 input projection (K = 2H)
    {
        dim3 grid(G4 / 128, (Bq * Wq) / 128, 2);
        gemm_tf32<1><<<grid, 256, P_SMEM>>>(hseq, 0,
                                            wr + OFF_WIH1, (size_t)G4 * 2 * Hq,
                                            b1,
                                            xg, (size_t)Bq * Wq * G4,
                                            Bq * Wq, G4, 2 * Hq);
    }

    // 5) layer-1 recurrence (hseq full fp32 -> feeds gather)
    lstm_persist<0><<<NCTA, 256, R_SMEM>>>(wr + OFF_WHH1, xg, Wq);

    // 6) gather
    gather_kernel<<<(Bq * 2 * Hq + 255) / 256, 256>>>(qlen, out);
}

// round 10
// speedup vs baseline: 1.6434x; 1.6434x over previous
#include <cuda_runtime.h>
#include <cuda_fp16.h>
#include <math.h>
#include <stdint.h>

#define Bq 512
#define Wq 40
#define Vq 12000
#define Eq 512
#define Hq 512
#define G4 2048   // 4*H
#define NCTA 128

// ---------------- scratch (device globals; no allocation) ----------------
__device__ __half g_table[(size_t)Vq * Eq];       // half tanh(lut^T)
__device__ __half g_emb[Bq * Wq * Eq];            // half embeddings
__device__ float g_xg[2 * (size_t)Bq * Wq * G4];  // per-dir input projections (f32)
__device__ float g_hseq[Bq * Wq * 2 * Hq];        // layer-1 output (f32, for gather)
__device__ __half g_hseq_h[Bq * Wq * 2 * Hq];     // layer-0 output (half, feeds proj-1)
__device__ __half g_ha[2][2 * Bq * Hq];           // h ping-pong (half, GEMM A)
__device__ float g_c[2 * Bq * Hq];
__device__ __half g_wr[10485760];                 // half weights: wih0|whh0|wih1|whh1
__device__ unsigned g_bar[2 * Wq];

#define OFF_WIH0 0
#define OFF_WHH0 2097152
#define OFF_WIH1 4194304
#define OFF_WHH1 8388608

__device__ __forceinline__ float sig_fast(float x) {
    return __fdividef(1.0f, 1.0f + __expf(-x));
}
__device__ __forceinline__ float tanh_fast(float x) {
    return 2.0f * __fdividef(1.0f, 1.0f + __expf(-2.0f * x)) - 1.0f;
}
__device__ __forceinline__ void cp16(uint32_t dst, const void* src) {
    asm volatile("cp.async.cg.shared.global [%0], [%1], 16;" :: "r"(dst), "l"(src));
}

__global__ void zero_bar_kernel() {
    if (threadIdx.x < 2 * Wq) g_bar[threadIdx.x] = 0;
}

// ---------------- one-time weight cvt to half ----------------
__global__ void cvt_weights_kernel(const float* __restrict__ src, int dstOff, int n) {
    int i = blockIdx.x * blockDim.x + threadIdx.x;
    if (i < n) g_wr[dstOff + i] = __float2half_rn(src[i]);
}

// ---------------- tanh + transpose lookup: g_table[v][e] = h(tanh(lut[e][v])) ----
__global__ void tanh_transpose_kernel(const float* __restrict__ lut) {
    __shared__ float tile[32][33];
    int v0 = blockIdx.x * 32;
    int e0 = blockIdx.y * 32;
    int tx = threadIdx.x, ty = threadIdx.y;
#pragma unroll
    for (int i = ty; i < 32; i += 8) {
        int e = e0 + i, v = v0 + tx;
        tile[i][tx] = (v < Vq) ? lut[(size_t)e * Vq + v] : 0.0f;
    }
    __syncthreads();
#pragma unroll
    for (int i = ty; i < 32; i += 8) {
        int v = v0 + i, e = e0 + tx;
        if (v < Vq) g_table[(size_t)v * Eq + e] = __float2half_rn(tanhf(tile[tx][i]));
    }
}

// ---------------- embedding gather (u32 granularity = 2 halves) ----------------
__global__ void embed_kernel(const int* __restrict__ ques) {
    int idx = blockIdx.x * blockDim.x + threadIdx.x;   // over u32s
    if (idx >= Bq * Wq * Eq / 2) return;
    int e2 = idx & 255;            // u32 within 512-half row
    int bw = idx >> 8;
    int v = ques[bw];
    uint32_t val = 0;
    if (v > 0) val = ((const uint32_t*)g_table)[(size_t)(v - 1) * 256 + e2];
    ((uint32_t*)g_emb)[idx] = val;
}

// ---------------- FP16 tensor-core NT GEMM, 4-stage cp.async ----------------
// C[dir](MxN f32) = A[dir](MxK half rm) @ Bw[dir](NxK half rm)^T + bias.
// 128x128 tile, BK=32 halves. Smem row: 16 u32 data + 4 pad = stride 20.
#define P_ASZ (128 * 20)            // u32 per stage
#define P_SMEM (4 * P_ASZ * 2 * 4)  // 81920 B
template <int HAS_BIAS>
__global__ __launch_bounds__(256, 2) void gemm_hf(
    const __half* __restrict__ A, size_t aDirStride,
    const __half* __restrict__ Bw, size_t bDirStride,
    const float* __restrict__ bias,
    float* __restrict__ C, size_t cDirStride,
    int M, int N, int K)
{
    extern __shared__ uint32_t sm[];
    uint32_t* smA = sm;                 // [4][128][20]
    uint32_t* smB = sm + 4 * P_ASZ;
    uint32_t baseA = (uint32_t)__cvta_generic_to_shared(smA);
    uint32_t baseB = (uint32_t)__cvta_generic_to_shared(smB);

    int dir = blockIdx.z;
    A  += (size_t)dir * aDirStride;
    Bw += (size_t)dir * bDirStride;
    C  += (size_t)dir * cDirStride;

    int m0 = blockIdx.y * 128;
    int n0 = blockIdx.x * 128;
    int tid = threadIdx.x;
    int wid = tid >> 5, lane = tid & 31;
    int wm = wid >> 2, wn = wid & 3;
    int gid = lane >> 2, tg = lane & 3;

    float acc[4][4][4];
#pragma unroll
    for (int mt = 0; mt < 4; mt++)
#pragma unroll
        for (int nt = 0; nt < 4; nt++)
#pragma unroll
            for (int r = 0; r < 4; r++) acc[mt][nt][r] = 0.0f;

    int niter = K >> 5;                 // BK = 32 halves

    auto load_stage = [&](int s, int k0) {
#pragma unroll
        for (int i = 0; i < 2; i++) {
            int c = tid + i * 256;               // 0..511
            int row = c >> 2, seg = c & 3;       // 4 segs of 8 halves
            cp16(baseA + (s * P_ASZ + row * 20 + seg * 4) * 4,
                 A + (size_t)(m0 + row) * K + k0 + seg * 8);
            cp16(baseB + (s * P_ASZ + row * 20 + seg * 4) * 4,
                 Bw + (size_t)(n0 + row) * K + k0 + seg * 8);
        }
        asm volatile("cp.async.commit_group;");
    };

    load_stage(0, 0);
    load_stage(1, 32);
    load_stage(2, 64);

    for (int it = 0; it < niter; it++) {
        int rem = niter - 1 - it;
        if (rem >= 2)      asm volatile("cp.async.wait_group 2;");
        else if (rem == 1) asm volatile("cp.async.wait_group 1;");
        else               asm volatile("cp.async.wait_group 0;");
        __syncthreads();
        if (it + 3 < niter) load_stage((it + 3) & 3, (it + 3) * 32);

        const uint32_t* Asb = smA + (it & 3) * P_ASZ;
        const uint32_t* Bsb = smB + (it & 3) * P_ASZ;
#pragma unroll
        for (int g = 0; g < 2; g++) {           // two k16 groups
            int kb = g * 8;                      // u32 base
            uint32_t af[4][4], bf[4][2];
#pragma unroll
            for (int mt = 0; mt < 4; mt++) {
                int m = wm * 64 + mt * 16 + gid;
                af[mt][0] = Asb[m * 20 + kb + tg];
                af[mt][1] = Asb[(m + 8) * 20 + kb + tg];
                af[mt][2] = Asb[m * 20 + kb + tg + 4];
                af[mt][3] = Asb[(m + 8) * 20 + kb + tg + 4];
            }
#pragma unroll
            for (int nt = 0; nt < 4; nt++) {
                int n = wn * 32 + nt * 8 + gid;
                bf[nt][0] = Bsb[n * 20 + kb + tg];
                bf[nt][1] = Bsb[n * 20 + kb + tg + 4];
            }
#pragma unroll
            for (int mt = 0; mt < 4; mt++)
#pragma unroll
                for (int nt = 0; nt < 4; nt++) {
                    asm volatile(
                        "mma.sync.aligned.m16n8k16.row.col.f32.f16.f16.f32 "
                        "{%0,%1,%2,%3}, {%4,%5,%6,%7}, {%8,%9}, {%0,%1,%2,%3};"
                        : "+f"(acc[mt][nt][0]), "+f"(acc[mt][nt][1]),
                          "+f"(acc[mt][nt][2]), "+f"(acc[mt][nt][3])
                        : "r"(af[mt][0]), "r"(af[mt][1]), "r"(af[mt][2]), "r"(af[mt][3]),
                          "r"(bf[nt][0]), "r"(bf[nt][1]));
                }
        }
    }

    const float* bp = bias + (size_t)dir * 2 * G4;
#pragma unroll
    for (int mt = 0; mt < 4; mt++) {
#pragma unroll
        for (int nt = 0; nt < 4; nt++) {
            int m = m0 + wm * 64 + mt * 16 + gid;
            int n = n0 + wn * 32 + nt * 8 + tg * 2;
            float2 v0, v1;
            v0.x = acc[mt][nt][0]; v0.y = acc[mt][nt][1];
            v1.x = acc[mt][nt][2]; v1.y = acc[mt][nt][3];
            if (HAS_BIAS) {
                float bx = bp[n] + bp[G4 + n];
                float by = bp[n + 1] + bp[G4 + n + 1];
                v0.x += bx; v0.y += by; v1.x += bx; v1.y += by;
            }
            *(float2*)(C + (size_t)m * N + n) = v0;
            *(float2*)(C + (size_t)(m + 8) * N + n) = v1;
        }
    }
}

// ---------------- persistent fused LSTM recurrence (fp16 mma) ----------------
// 128 CTAs: dir(2) x m-tiles(8) x h-tiles(8). Per step: gates[64x256] =
// h[64x512]h @ whh strips[256x512]h^T. BK=64 halves, 8 chunks, 4-stage cp.async.
// LAYER0=1 -> hseq written half (feeds proj-1); else f32 (feeds gather).
#define R_ASZ (64 * 36)         // u32 per A stage (64 rows x (32+4) u32)
#define R_BSZ (256 * 36)        // u32 per B stage
#define R_SMEM (4 * (R_ASZ + R_BSZ) * 4)   // 184320 B
#define GSM_STRIDE 258
template <int LAYER0>
__global__ __launch_bounds__(256) void lstm_persist(
    const __half* __restrict__ whh,      // [2 dirs][G4][Hq] half
    const float* __restrict__ xg,        // [2 dirs][Bq][Wq][G4] f32
    int bar_ofs)
{
    extern __shared__ uint32_t sm[];
    uint32_t* smA = sm;                   // [4][64][36]
    uint32_t* smB = sm + 4 * R_ASZ;       // [4][256][36]
    float* gsm = (float*)sm;              // epilogue alias [64][258]
    uint32_t baseA = (uint32_t)__cvta_generic_to_shared(smA);
    uint32_t baseB = (uint32_t)__cvta_generic_to_shared(smB);

    int tid = threadIdx.x;
    int bx = blockIdx.x;
    int dir = bx >> 6;
    int r = bx & 63;
    int m0 = (r >> 3) * 64;
    int ht0 = (r & 7) * 64;

    int wid = tid >> 5, lane = tid & 31;
    int wm = wid >> 2, wn = wid & 3;      // warp tile: 32 m x 64 n
    int gid = lane >> 2, tg = lane & 3;

    const __half* wbase = whh + (size_t)dir * G4 * Hq;
    const float* xgd = xg + (size_t)dir * Bq * Wq * G4;

    for (int step = 0; step < Wq; step++) {
        float acc[2][8][4];
#pragma unroll
        for (int mt = 0; mt < 2; mt++)
#pragma unroll
            for (int t = 0; t < 8; t++)
#pragma unroll
                for (int q = 0; q < 4; q++) acc[mt][t][q] = 0.0f;

        if (step > 0) {
            const __half* habase = g_ha[(step - 1) & 1] + dir * Bq * Hq;

            auto load_stage = [&](int s, int k0) {
#pragma unroll
                for (int i = 0; i < 2; i++) {
                    int c = tid + i * 256;           // 0..511
                    int row = c >> 3, seg = c & 7;   // 8 segs of 8 halves
                    cp16(baseA + (s * R_ASZ + row * 36 + seg * 4) * 4,
                         habase + (size_t)(m0 + row) * Hq + k0 + seg * 8);
                }
#pragma unroll
                for (int i = 0; i < 8; i++) {
                    int c = tid + i * 256;           // 0..2047
                    int row = c >> 3, seg = c & 7;
                    int grow = ((row >> 6) << 9) + ht0 + (row & 63);
                    cp16(baseB + (s * R_BSZ + row * 36 + seg * 4) * 4,
                         wbase + (size_t)grow * Hq + k0 + seg * 8);
                }
                asm volatile("cp.async.commit_group;");
            };

            load_stage(0, 0);
            load_stage(1, 64);
            load_stage(2, 128);

            for (int kc = 0; kc < 8; kc++) {        // BK = 64 halves
                int rem = 7 - kc;
                if (rem >= 2)      asm volatile("cp.async.wait_group 2;");
                else if (rem == 1) asm volatile("cp.async.wait_group 1;");
                else               asm volatile("cp.async.wait_group 0;");
                __syncthreads();
                if (kc + 3 < 8) load_stage((kc + 3) & 3, (kc + 3) * 64);

                const uint32_t* Asb = smA + (kc & 3) * R_ASZ;
                const uint32_t* Bsb = smB + (kc & 3) * R_BSZ;
#pragma unroll
                for (int g = 0; g < 4; g++) {        // four k16 groups
                    int kb = g * 8;
                    uint32_t af[2][4], bf[8][2];
#pragma unroll
                    for (int mt = 0; mt < 2; mt++) {
                        int mr = wm * 32 + mt * 16 + gid;
                        af[mt][0] = Asb[mr * 36 + kb + tg];
                        af[mt][1] = Asb[(mr + 8) * 36 + kb + tg];
                        af[mt][2] = Asb[mr * 36 + kb + tg + 4];
                        af[mt][3] = Asb[(mr + 8) * 36 + kb + tg + 4];
                    }
#pragma unroll
                    for (int t = 0; t < 8; t++) {
                        int br = ((t >> 1) << 6) + wn * 16 + ((t & 1) << 3) + gid;
                        bf[t][0] = Bsb[br * 36 + kb + tg];
                        bf[t][1] = Bsb[br * 36 + kb + tg + 4];
                    }
#pragma unroll
                    for (int mt = 0; mt < 2; mt++)
#pragma unroll
                        for (int t = 0; t < 8; t++) {
                            asm volatile(
                                "mma.sync.aligned.m16n8k16.row.col.f32.f16.f16.f32 "
                                "{%0,%1,%2,%3}, {%4,%5,%6,%7}, {%8,%9}, {%0,%1,%2,%3};"
                                : "+f"(acc[mt][t][0]), "+f"(acc[mt][t][1]),
                                  "+f"(acc[mt][t][2]), "+f"(acc[mt][t][3])
                                : "r"(af[mt][0]), "r"(af[mt][1]), "r"(af[mt][2]), "r"(af[mt][3]),
                                  "r"(bf[t][0]), "r"(bf[t][1]));
                        }
                }
            }
        }

        // ---- stage gates into smem (reuses pipeline buffers) ----
        __syncthreads();
#pragma unroll
        for (int mt = 0; mt < 2; mt++)
#pragma unroll
            for (int t = 0; t < 8; t++)
#pragma unroll
                for (int rs = 0; rs < 2; rs++) {
                    int mr = wm * 32 + mt * 16 + gid + rs * 8;
                    int nc = ((t >> 1) << 6) + wn * 16 + ((t & 1) << 3) + tg * 2;
                    float2 v;
                    v.x = acc[mt][t][rs * 2];
                    v.y = acc[mt][t][rs * 2 + 1];
                    *(float2*)&gsm[mr * GSM_STRIDE + nc] = v;
                }
        __syncthreads();

        // ---- coalesced fused gate epilogue ----
        int t_ = dir ? (Wq - 1 - step) : step;
        __half* haw = g_ha[step & 1] + dir * Bq * Hq;
        int hl = (tid & 31) * 2;
        int mb = tid >> 5;
#pragma unroll
        for (int mm = 0; mm < 8; mm++) {
            int m = mb + mm * 8;
            int gm = m0 + m;
            const float* gr = &gsm[m * GSM_STRIDE];
            const float* xp = xgd + ((size_t)gm * Wq + t_) * G4 + ht0 + hl;
            float2 gi = *(const float2*)&gr[hl];
            float2 gf = *(const float2*)&gr[64 + hl];
            float2 gg = *(const float2*)&gr[128 + hl];
            float2 go = *(const float2*)&gr[192 + hl];
            float2 xi = *(const float2*)&xp[0];
            float2 xf = *(const float2*)&xp[512];
            float2 xgg = *(const float2*)&xp[1024];
            float2 xo = *(const float2*)&xp[1536];
            int ci = dir * Bq * Hq + gm * Hq + ht0 + hl;
            float2 cprev = (step == 0) ? make_float2(0.f, 0.f) : *(const float2*)&g_c[ci];
            float2 cv, hv;
            cv.x = sig_fast(gf.x + xf.x) * cprev.x + sig_fast(gi.x + xi.x) * tanh_fast(gg.x + xgg.x);
            cv.y = sig_fast(gf.y + xf.y) * cprev.y + sig_fast(gi.y + xi.y) * tanh_fast(gg.y + xgg.y);
            hv.x = sig_fast(go.x + xo.x) * tanh_fast(cv.x);
            hv.y = sig_fast(go.y + xo.y) * tanh_fast(cv.y);
            *(float2*)&g_c[ci] = cv;
            __half2 hh = __floats2half2_rn(hv.x, hv.y);
            *(__half2*)&haw[gm * Hq + ht0 + hl] = hh;
            size_t so = ((size_t)gm * Wq + t_) * (2 * Hq) + dir * Hq + ht0 + hl;
            if (LAYER0) {
                *(__half2*)&g_hseq_h[so] = hh;
            } else {
                *(float2*)&g_hseq[so] = hv;
            }
        }

        // ---- grid barrier ----
        if (step < Wq - 1) {
            __threadfence();
            __syncthreads();
            if (tid == 0) {
                unsigned* ctr = &g_bar[bar_ofs + step];
                atomicAdd(ctr, 1u);
                unsigned v;
                do {
                    asm volatile("ld.acquire.gpu.u32 %0, [%1];"
                                 : "=r"(v) : "l"(ctr) : "memory");
                    if (v < NCTA) __nanosleep(64);
                } while (v < NCTA);
            }
            __syncthreads();
        }
    }
}

// ---------------- final gather at t = len-1 ----------------
__global__ void gather_kernel(const int* __restrict__ qlen, float* __restrict__ out) {
    int idx = blockIdx.x * blockDim.x + threadIdx.x;
    if (idx >= Bq * 2 * Hq) return;
    int b = idx / (2 * Hq);
    int j = idx - b * (2 * Hq);
    int t = qlen[b] - 1;
    out[idx] = g_hseq[((size_t)b * Wq + t) * (2 * Hq) + j];
}

// ---------------- launch ----------------
extern "C" void kernel_launch(void* const* d_in, const int* in_sizes, int n_in,
                              void* d_out, int out_size)
{
    const int*   ques = (const int*)d_in[0];
    const int*   qlen = (const int*)d_in[1];
    const float* lut  = (const float*)d_in[2];
    const float* wih0 = (const float*)d_in[3];
    const float* whh0 = (const float*)d_in[4];
    const float* b0   = (const float*)d_in[5];
    const float* wih1 = (const float*)d_in[6];
    const float* whh1 = (const float*)d_in[7];
    const float* b1   = (const float*)d_in[8];
    float* out = (float*)d_out;

    __half *emb, *hseq_h, *wr;
    float *xg;
    cudaGetSymbolAddress((void**)&emb,    g_emb);
    cudaGetSymbolAddress((void**)&xg,     g_xg);
    cudaGetSymbolAddress((void**)&hseq_h, g_hseq_h);
    cudaGetSymbolAddress((void**)&wr,     g_wr);

    cudaFuncSetAttribute(gemm_hf<1>, cudaFuncAttributeMaxDynamicSharedMemorySize, P_SMEM);
    cudaFuncSetAttribute(lstm_persist<0>, cudaFuncAttributeMaxDynamicSharedMemorySize, R_SMEM);
    cudaFuncSetAttribute(lstm_persist<1>, cudaFuncAttributeMaxDynamicSharedMemorySize, R_SMEM);

    // 0) barriers + half weights + table
    zero_bar_kernel<<<1, 128>>>();
    cvt_weights_kernel<<<(2097152 + 255) / 256, 256>>>(wih0, OFF_WIH0, 2097152);
    cvt_weights_kernel<<<(2097152 + 255) / 256, 256>>>(whh0, OFF_WHH0, 2097152);
    cvt_weights_kernel<<<(4194304 + 255) / 256, 256>>>(wih1, OFF_WIH1, 4194304);
    cvt_weights_kernel<<<(2097152 + 255) / 256, 256>>>(whh1, OFF_WHH1, 2097152);
    {
        dim3 grid((Vq + 31) / 32, Eq / 32);
        tanh_transpose_kernel<<<grid, dim3(32, 8)>>>(lut);
    }

    // 1) embedding
    embed_kernel<<<(Bq * Wq * Eq / 2 + 255) / 256, 256>>>(ques);

    // 2) layer-0 input projection (fp16 mma)
    {
        dim3 grid(G4 / 128, (Bq * Wq) / 128, 2);
        gemm_hf<1><<<grid, 256, P_SMEM>>>(emb, 0,
                                          wr + OFF_WIH0, (size_t)G4 * Eq,
                                          b0,
                                          xg, (size_t)Bq * Wq * G4,
                                          Bq * Wq, G4, Eq);
    }

    // 3) layer-0 recurrence (writes half hseq)
    lstm_persist<1><<<NCTA, 256, R_SMEM>>>(wr + OFF_WHH0, xg, 0);

    // 4) layer-1 input projection (K = 2H, A = half hseq)
    {
        dim3 grid(G4 / 128, (Bq * Wq) / 128, 2);
        gemm_hf<1><<<grid, 256, P_SMEM>>>(hseq_h, 0,
                                          wr + OFF_WIH1, (size_t)G4 * 2 * Hq,
                                          b1,
                                          xg, (size_t)Bq * Wq * G4,
                                          Bq * Wq, G4, 2 * Hq);
    }

    // 5) layer-1 recurrence (writes f32 hseq for gather)
    lstm_persist<0><<<NCTA, 256, R_SMEM>>>(wr + OFF_WHH1, xg, Wq);

    // 6) gather
    gather_kernel<<<(Bq * 2 * Hq + 255) / 256, 256>>>(qlen, out);
}

// round 11
// speedup vs baseline: 1.6857x; 1.0257x over previous
#include <cuda_runtime.h>
#include <cuda_fp16.h>
#include <math.h>
#include <stdint.h>

#define Bq 512
#define Wq 40
#define Vq 12000
#define Eq 512
#define Hq 512
#define G4 2048   // 4*H
#define NCTA 128

// ---------------- scratch (device globals; no allocation) ----------------
__device__ __half g_table[(size_t)Vq * Eq];       // half tanh(lut^T)
__device__ __half g_emb[Bq * Wq * Eq];            // half embeddings
__device__ float g_xg[2 * (size_t)Bq * Wq * G4];  // per-dir input projections (f32)
__device__ float g_hseq[Bq * Wq * 2 * Hq];        // layer-1 output (f32, for gather)
__device__ __half g_hseq_h[Bq * Wq * 2 * Hq];     // layer-0 output (half, feeds proj-1)
__device__ __half g_ha[2][2 * Bq * Hq];           // h ping-pong (half, GEMM A)
__device__ float g_c[2 * Bq * Hq];
__device__ __half g_wr[10485760];                 // half weights: wih0|whh0|wih1|whh1
__device__ unsigned g_bar[2 * Wq];

#define OFF_WIH0 0
#define OFF_WHH0 2097152
#define OFF_WIH1 4194304
#define OFF_WHH1 8388608
#define W_TOTAL  10485760

__device__ __forceinline__ float sig_fast(float x) {
    return __fdividef(1.0f, 1.0f + __expf(-x));
}
__device__ __forceinline__ float tanh_fast(float x) {
    return 2.0f * __fdividef(1.0f, 1.0f + __expf(-2.0f * x)) - 1.0f;
}
__device__ __forceinline__ void cp16(uint32_t dst, const void* src) {
    asm volatile("cp.async.cg.shared.global [%0], [%1], 16;" :: "r"(dst), "l"(src));
}

// ---------------- one-time: all weights -> half, zero barriers (fused) ----------
__global__ void cvt_all_weights_kernel(const float* __restrict__ w0, const float* __restrict__ w1,
                                       const float* __restrict__ w2, const float* __restrict__ w3) {
    int i = blockIdx.x * blockDim.x + threadIdx.x;     // one thread = 4 floats
    if (blockIdx.x == 0 && threadIdx.x < 2 * Wq) g_bar[threadIdx.x] = 0;
    int idx4 = i * 4;
    if (idx4 >= W_TOTAL) return;
    const float* src; int off;
    if (idx4 < OFF_WHH0)      { src = w0; off = idx4; }
    else if (idx4 < OFF_WIH1) { src = w1; off = idx4 - OFF_WHH0; }
    else if (idx4 < OFF_WHH1) { src = w2; off = idx4 - OFF_WIH1; }
    else                      { src = w3; off = idx4 - OFF_WHH1; }
    float4 v = *(const float4*)(src + off);
    __half2 a = __floats2half2_rn(v.x, v.y);
    __half2 b = __floats2half2_rn(v.z, v.w);
    __half2* dst = (__half2*)&g_wr[idx4];
    dst[0] = a; dst[1] = b;
}

// ---------------- tanh + transpose lookup: g_table[v][e] = h(tanh(lut[e][v])) ----
__global__ void tanh_transpose_kernel(const float* __restrict__ lut) {
    __shared__ float tile[32][33];
    int v0 = blockIdx.x * 32;
    int e0 = blockIdx.y * 32;
    int tx = threadIdx.x, ty = threadIdx.y;
#pragma unroll
    for (int i = ty; i < 32; i += 8) {
        int e = e0 + i, v = v0 + tx;
        tile[i][tx] = (v < Vq) ? lut[(size_t)e * Vq + v] : 0.0f;
    }
    __syncthreads();
#pragma unroll
    for (int i = ty; i < 32; i += 8) {
        int v = v0 + i, e = e0 + tx;
        if (v < Vq) g_table[(size_t)v * Eq + e] = __float2half_rn(tanhf(tile[tx][i]));
    }
}

// ---------------- embedding gather (u32 granularity = 2 halves) ----------------
__global__ void embed_kernel(const int* __restrict__ ques) {
    int idx = blockIdx.x * blockDim.x + threadIdx.x;   // over u32s
    if (idx >= Bq * Wq * Eq / 2) return;
    int e2 = idx & 255;
    int bw = idx >> 8;
    int v = ques[bw];
    uint32_t val = 0;
    if (v > 0) val = ((const uint32_t*)g_table)[(size_t)(v - 1) * 256 + e2];
    ((uint32_t*)g_emb)[idx] = val;
}

// ---------------- FP16 tensor-core NT GEMM, 4-stage cp.async ----------------
#define P_ASZ (128 * 20)            // u32 per stage
#define P_SMEM (4 * P_ASZ * 2 * 4)  // 81920 B
template <int HAS_BIAS>
__global__ __launch_bounds__(256, 2) void gemm_hf(
    const __half* __restrict__ A, size_t aDirStride,
    const __half* __restrict__ Bw, size_t bDirStride,
    const float* __restrict__ bias,
    float* __restrict__ C, size_t cDirStride,
    int M, int N, int K)
{
    extern __shared__ uint32_t sm[];
    uint32_t* smA = sm;                 // [4][128][20]
    uint32_t* smB = sm + 4 * P_ASZ;
    uint32_t baseA = (uint32_t)__cvta_generic_to_shared(smA);
    uint32_t baseB = (uint32_t)__cvta_generic_to_shared(smB);

    int dir = blockIdx.z;
    A  += (size_t)dir * aDirStride;
    Bw += (size_t)dir * bDirStride;
    C  += (size_t)dir * cDirStride;

    int m0 = blockIdx.y * 128;
    int n0 = blockIdx.x * 128;
    int tid = threadIdx.x;
    int wid = tid >> 5, lane = tid & 31;
    int wm = wid >> 2, wn = wid & 3;
    int gid = lane >> 2, tg = lane & 3;

    float acc[4][4][4];
#pragma unroll
    for (int mt = 0; mt < 4; mt++)
#pragma unroll
        for (int nt = 0; nt < 4; nt++)
#pragma unroll
            for (int r = 0; r < 4; r++) acc[mt][nt][r] = 0.0f;

    int niter = K >> 5;                 // BK = 32 halves

    auto load_stage = [&](int s, int k0) {
#pragma unroll
        for (int i = 0; i < 2; i++) {
            int c = tid + i * 256;
            int row = c >> 2, seg = c & 3;
            cp16(baseA + (s * P_ASZ + row * 20 + seg * 4) * 4,
                 A + (size_t)(m0 + row) * K + k0 + seg * 8);
            cp16(baseB + (s * P_ASZ + row * 20 + seg * 4) * 4,
                 Bw + (size_t)(n0 + row) * K + k0 + seg * 8);
        }
        asm volatile("cp.async.commit_group;");
    };

    load_stage(0, 0);
    load_stage(1, 32);
    load_stage(2, 64);

    for (int it = 0; it < niter; it++) {
        int rem = niter - 1 - it;
        if (rem >= 2)      asm volatile("cp.async.wait_group 2;");
        else if (rem == 1) asm volatile("cp.async.wait_group 1;");
        else               asm volatile("cp.async.wait_group 0;");
        __syncthreads();
        if (it + 3 < niter) load_stage((it + 3) & 3, (it + 3) * 32);

        const uint32_t* Asb = smA + (it & 3) * P_ASZ;
        const uint32_t* Bsb = smB + (it & 3) * P_ASZ;
#pragma unroll
        for (int g = 0; g < 2; g++) {
            int kb = g * 8;
            uint32_t af[4][4], bf[4][2];
#pragma unroll
            for (int mt = 0; mt < 4; mt++) {
                int m = wm * 64 + mt * 16 + gid;
                af[mt][0] = Asb[m * 20 + kb + tg];
                af[mt][1] = Asb[(m + 8) * 20 + kb + tg];
                af[mt][2] = Asb[m * 20 + kb + tg + 4];
                af[mt][3] = Asb[(m + 8) * 20 + kb + tg + 4];
            }
#pragma unroll
            for (int nt = 0; nt < 4; nt++) {
                int n = wn * 32 + nt * 8 + gid;
                bf[nt][0] = Bsb[n * 20 + kb + tg];
                bf[nt][1] = Bsb[n * 20 + kb + tg + 4];
            }
#pragma unroll
            for (int mt = 0; mt < 4; mt++)
#pragma unroll
                for (int nt = 0; nt < 4; nt++) {
                    asm volatile(
                        "mma.sync.aligned.m16n8k16.row.col.f32.f16.f16.f32 "
                        "{%0,%1,%2,%3}, {%4,%5,%6,%7}, {%8,%9}, {%0,%1,%2,%3};"
                        : "+f"(acc[mt][nt][0]), "+f"(acc[mt][nt][1]),
                          "+f"(acc[mt][nt][2]), "+f"(acc[mt][nt][3])
                        : "r"(af[mt][0]), "r"(af[mt][1]), "r"(af[mt][2]), "r"(af[mt][3]),
                          "r"(bf[nt][0]), "r"(bf[nt][1]));
                }
        }
    }

    const float* bp = bias + (size_t)dir * 2 * G4;
#pragma unroll
    for (int mt = 0; mt < 4; mt++) {
#pragma unroll
        for (int nt = 0; nt < 4; nt++) {
            int m = m0 + wm * 64 + mt * 16 + gid;
            int n = n0 + wn * 32 + nt * 8 + tg * 2;
            float2 v0, v1;
            v0.x = acc[mt][nt][0]; v0.y = acc[mt][nt][1];
            v1.x = acc[mt][nt][2]; v1.y = acc[mt][nt][3];
            if (HAS_BIAS) {
                float bx = bp[n] + bp[G4 + n];
                float by = bp[n + 1] + bp[G4 + n + 1];
                v0.x += bx; v0.y += by; v1.x += bx; v1.y += by;
            }
            *(float2*)(C + (size_t)m * N + n) = v0;
            *(float2*)(C + (size_t)(m + 8) * N + n) = v1;
        }
    }
}

// ---------------- persistent fused LSTM recurrence (fp16 mma) ----------------
// 3-stage cp.async + dedicated gate-staging smem; next-step weight chunks
// B0,B1 prefetched across the grid barrier (weights are step-invariant).
#define R_ASZ (64 * 36)         // u32 per A stage
#define R_BSZ (256 * 36)        // u32 per B stage
#define R_GSM (3 * (R_ASZ + R_BSZ))          // u32 offset of gate staging
#define R_SMEM ((R_GSM + 64 * 258) * 4)      // 204288 B
#define GSM_STRIDE 258
template <int LAYER0>
__global__ __launch_bounds__(256) void lstm_persist(
    const __half* __restrict__ whh,      // [2 dirs][G4][Hq] half
    const float* __restrict__ xg,        // [2 dirs][Bq][Wq][G4] f32
    int bar_ofs)
{
    extern __shared__ uint32_t sm[];
    uint32_t* smA = sm;                   // [3][64][36]
    uint32_t* smB = sm + 3 * R_ASZ;       // [3][256][36]
    float* gsm = (float*)(sm + R_GSM);    // [64][258] dedicated
    uint32_t baseA = (uint32_t)__cvta_generic_to_shared(smA);
    uint32_t baseB = (uint32_t)__cvta_generic_to_shared(smB);

    int tid = threadIdx.x;
    int bx = blockIdx.x;
    int dir = bx >> 6;
    int r = bx & 63;
    int m0 = (r >> 3) * 64;
    int ht0 = (r & 7) * 64;

    int wid = tid >> 5, lane = tid & 31;
    int wm = wid >> 2, wn = wid & 3;      // warp tile: 32 m x 64 n
    int gid = lane >> 2, tg = lane & 3;

    const __half* wbase = whh + (size_t)dir * G4 * Hq;
    const float* xgd = xg + (size_t)dir * Bq * Wq * G4;

    auto load_A = [&](int s, int k0, const __half* habase) {
#pragma unroll
        for (int i = 0; i < 2; i++) {
            int c = tid + i * 256;
            int row = c >> 3, seg = c & 7;
            cp16(baseA + (s * R_ASZ + row * 36 + seg * 4) * 4,
                 habase + (size_t)(m0 + row) * Hq + k0 + seg * 8);
        }
        asm volatile("cp.async.commit_group;");
    };
    auto load_B = [&](int s, int k0) {
#pragma unroll
        for (int i = 0; i < 8; i++) {
            int c = tid + i * 256;
            int row = c >> 3, seg = c & 7;
            int grow = ((row >> 6) << 9) + ht0 + (row & 63);
            cp16(baseB + (s * R_BSZ + row * 36 + seg * 4) * 4,
                 wbase + (size_t)grow * Hq + k0 + seg * 8);
        }
        asm volatile("cp.async.commit_group;");
    };
    auto load_AB = [&](int s, int k0, const __half* habase) {
#pragma unroll
        for (int i = 0; i < 2; i++) {
            int c = tid + i * 256;
            int row = c >> 3, seg = c & 7;
            cp16(baseA + (s * R_ASZ + row * 36 + seg * 4) * 4,
                 habase + (size_t)(m0 + row) * Hq + k0 + seg * 8);
        }
#pragma unroll
        for (int i = 0; i < 8; i++) {
            int c = tid + i * 256;
            int row = c >> 3, seg = c & 7;
            int grow = ((row >> 6) << 9) + ht0 + (row & 63);
            cp16(baseB + (s * R_BSZ + row * 36 + seg * 4) * 4,
                 wbase + (size_t)grow * Hq + k0 + seg * 8);
        }
        asm volatile("cp.async.commit_group;");
    };

    for (int step = 0; step < Wq; step++) {
        float acc[2][8][4];
#pragma unroll
        for (int mt = 0; mt < 2; mt++)
#pragma unroll
            for (int t = 0; t < 8; t++)
#pragma unroll
                for (int q = 0; q < 4; q++) acc[mt][t][q] = 0.0f;

        if (step > 0) {
            const __half* habase = g_ha[(step - 1) & 1] + dir * Bq * Hq;
            // B0,B1 already in flight (prefetched before the barrier).
            load_A(0, 0, habase);
            load_A(1, 64, habase);

            for (int kc = 0; kc < 8; kc++) {       // BK = 64 halves, stages kc%3
                if (kc < 7) asm volatile("cp.async.wait_group 1;");
                else        asm volatile("cp.async.wait_group 0;");
                __syncthreads();
                if (kc < 6) load_AB((kc + 2) % 3, (kc + 2) * 64, habase);

                const uint32_t* Asb = smA + (kc % 3) * R_ASZ;
                const uint32_t* Bsb = smB + (kc % 3) * R_BSZ;
#pragma unroll
                for (int g = 0; g < 4; g++) {
                    int kb = g * 8;
                    uint32_t af[2][4], bf[8][2];
#pragma unroll
                    for (int mt = 0; mt < 2; mt++) {
                        int mr = wm * 32 + mt * 16 + gid;
                        af[mt][0] = Asb[mr * 36 + kb + tg];
                        af[mt][1] = Asb[(mr + 8) * 36 + kb + tg];
                        af[mt][2] = Asb[mr * 36 + kb + tg + 4];
                        af[mt][3] = Asb[(mr + 8) * 36 + kb + tg + 4];
                    }
#pragma unroll
                    for (int t = 0; t < 8; t++) {
                        int br = ((t >> 1) << 6) + wn * 16 + ((t & 1) << 3) + gid;
                        bf[t][0] = Bsb[br * 36 + kb + tg];
                        bf[t][1] = Bsb[br * 36 + kb + tg + 4];
                    }
#pragma unroll
                    for (int mt = 0; mt < 2; mt++)
#pragma unroll
                        for (int t = 0; t < 8; t++) {
                            asm volatile(
                                "mma.sync.aligned.m16n8k16.row.col.f32.f16.f16.f32 "
                                "{%0,%1,%2,%3}, {%4,%5,%6,%7}, {%8,%9}, {%0,%1,%2,%3};"
                                : "+f"(acc[mt][t][0]), "+f"(acc[mt][t][1]),
                                  "+f"(acc[mt][t][2]), "+f"(acc[mt][t][3])
                                : "r"(af[mt][0]), "r"(af[mt][1]), "r"(af[mt][2]), "r"(af[mt][3]),
                                  "r"(bf[t][0]), "r"(bf[t][1]));
                        }
                }
            }
        }

        // all stages consumed; prefetch next step's weight chunks across the barrier
        __syncthreads();
        if (step < Wq - 1) {
            load_B(0, 0);
            load_B(1, 64);
        }

        // ---- stage gates into dedicated smem ----
#pragma unroll
        for (int mt = 0; mt < 2; mt++)
#pragma unroll
            for (int t = 0; t < 8; t++)
#pragma unroll
                for (int rs = 0; rs < 2; rs++) {
                    int mr = wm * 32 + mt * 16 + gid + rs * 8;
                    int nc = ((t >> 1) << 6) + wn * 16 + ((t & 1) << 3) + tg * 2;
                    float2 v;
                    v.x = acc[mt][t][rs * 2];
                    v.y = acc[mt][t][rs * 2 + 1];
                    *(float2*)&gsm[mr * GSM_STRIDE + nc] = v;
                }
        __syncthreads();

        // ---- coalesced fused gate epilogue ----
        int t_ = dir ? (Wq - 1 - step) : step;
        __half* haw = g_ha[step & 1] + dir * Bq * Hq;
        int hl = (tid & 31) * 2;
        int mb = tid >> 5;
#pragma unroll
        for (int mm = 0; mm < 8; mm++) {
            int m = mb + mm * 8;
            int gm = m0 + m;
            const float* gr = &gsm[m * GSM_STRIDE];
            const float* xp = xgd + ((size_t)gm * Wq + t_) * G4 + ht0 + hl;
            float2 gi = *(const float2*)&gr[hl];
            float2 gf = *(const float2*)&gr[64 + hl];
            float2 gg = *(const float2*)&gr[128 + hl];
            float2 go = *(const float2*)&gr[192 + hl];
            float2 xi = *(const float2*)&xp[0];
            float2 xf = *(const float2*)&xp[512];
            float2 xgg = *(const float2*)&xp[1024];
            float2 xo = *(const float2*)&xp[1536];
            int ci = dir * Bq * Hq + gm * Hq + ht0 + hl;
            float2 cprev = (step == 0) ? make_float2(0.f, 0.f) : *(const float2*)&g_c[ci];
            float2 cv, hv;
            cv.x = sig_fast(gf.x + xf.x) * cprev.x + sig_fast(gi.x + xi.x) * tanh_fast(gg.x + xgg.x);
            cv.y = sig_fast(gf.y + xf.y) * cprev.y + sig_fast(gi.y + xi.y) * tanh_fast(gg.y + xgg.y);
            hv.x = sig_fast(go.x + xo.x) * tanh_fast(cv.x);
            hv.y = sig_fast(go.y + xo.y) * tanh_fast(cv.y);
            *(float2*)&g_c[ci] = cv;
            __half2 hh = __floats2half2_rn(hv.x, hv.y);
            *(__half2*)&haw[gm * Hq + ht0 + hl] = hh;
            size_t so = ((size_t)gm * Wq + t_) * (2 * Hq) + dir * Hq + ht0 + hl;
            if (LAYER0) {
                *(__half2*)&g_hseq_h[so] = hh;
            } else {
                *(float2*)&g_hseq[so] = hv;
            }
        }

        // ---- grid barrier ----
        if (step < Wq - 1) {
            __threadfence();
            __syncthreads();
            if (tid == 0) {
                unsigned* ctr = &g_bar[bar_ofs + step];
                atomicAdd(ctr, 1u);
                unsigned v;
                do {
                    asm volatile("ld.acquire.gpu.u32 %0, [%1];"
                                 : "=r"(v) : "l"(ctr) : "memory");
                    if (v < NCTA) __nanosleep(64);
                } while (v < NCTA);
            }
            __syncthreads();
        }
    }
}

// ---------------- final gather at t = len-1 ----------------
__global__ void gather_kernel(const int* __restrict__ qlen, float* __restrict__ out) {
    int idx = blockIdx.x * blockDim.x + threadIdx.x;
    if (idx >= Bq * 2 * Hq) return;
    int b = idx / (2 * Hq);
    int j = idx - b * (2 * Hq);
    int t = qlen[b] - 1;
    out[idx] = g_hseq[((size_t)b * Wq + t) * (2 * Hq) + j];
}

// ---------------- launch ----------------
extern "C" void kernel_launch(void* const* d_in, const int* in_sizes, int n_in,
                              void* d_out, int out_size)
{
    const int*   ques = (const int*)d_in[0];
    const int*   qlen = (const int*)d_in[1];
    const float* lut  = (const float*)d_in[2];
    const float* wih0 = (const float*)d_in[3];
    const float* whh0 = (const float*)d_in[4];
    const float* b0   = (const float*)d_in[5];
    const float* wih1 = (const float*)d_in[6];
    const float* whh1 = (const float*)d_in[7];
    const float* b1   = (const float*)d_in[8];
    float* out = (float*)d_out;

    __half *emb, *hseq_h, *wr;
    float *xg;
    cudaGetSymbolAddress((void**)&emb,    g_emb);
    cudaGetSymbolAddress((void**)&xg,     g_xg);
    cudaGetSymbolAddress((void**)&hseq_h, g_hseq_h);
    cudaGetSymbolAddress((void**)&wr,     g_wr);

    cudaFuncSetAttribute(gemm_hf<1>, cudaFuncAttributeMaxDynamicSharedMemorySize, P_SMEM);
    cudaFuncSetAttribute(lstm_persist<0>, cudaFuncAttributeMaxDynamicSharedMemorySize, R_SMEM);
    cudaFuncSetAttribute(lstm_persist<1>, cudaFuncAttributeMaxDynamicSharedMemorySize, R_SMEM);

    // 0) fused: all weights -> half + barrier zeroing; table build
    cvt_all_weights_kernel<<<(W_TOTAL / 4 + 255) / 256, 256>>>(wih0, whh0, wih1, whh1);
    {
        dim3 grid((Vq + 31) / 32, Eq / 32);
        tanh_transpose_kernel<<<grid, dim3(32, 8)>>>(lut);
    }

    // 1) embedding
    embed_kernel<<<(Bq * Wq * Eq / 2 + 255) / 256, 256>>>(ques);

    // 2) layer-0 input projection (fp16 mma)
    {
        dim3 grid(G4 / 128, (Bq * Wq) / 128, 2);
        gemm_hf<1><<<grid, 256, P_SMEM>>>(emb, 0,
                                          wr + OFF_WIH0, (size_t)G4 * Eq,
                                          b0,
                                          xg, (size_t)Bq * Wq * G4,
                                          Bq * Wq, G4, Eq);
    }

    // 3) layer-0 recurrence (writes half hseq)
    lstm_persist<1><<<NCTA, 256, R_SMEM>>>(wr + OFF_WHH0, xg, 0);

    // 4) layer-1 input projection (K = 2H, A = half hseq)
    {
        dim3 grid(G4 / 128, (Bq * Wq) / 128, 2);
        gemm_hf<1><<<grid, 256, P_SMEM>>>(hseq_h, 0,
                                          wr + OFF_WIH1, (size_t)G4 * 2 * Hq,
                                          b1,
                                          xg, (size_t)Bq * Wq * G4,
                                          Bq * Wq, G4, 2 * Hq);
    }

    // 5) layer-1 recurrence (writes f32 hseq for gather)
    lstm_persist<0><<<NCTA, 256, R_SMEM>>>(wr + OFF_WHH1, xg, Wq);

    // 6) gather
    gather_kernel<<<(Bq * 2 * Hq + 255) / 256, 256>>>(qlen, out);
}

// round 12
// speedup vs baseline: 1.6994x; 1.0081x over previous
#include <cuda_runtime.h>
#include <cuda_fp16.h>
#include <math.h>
#include <stdint.h>

#define Bq 512
#define Wq 40
#define Vq 12000
#define Eq 512
#define Hq 512
#define G4 2048   // 4*H
#define NCTA 128

// ---------------- scratch (device globals; no allocation) ----------------
__device__ __half g_table[(size_t)Vq * Eq];       // half tanh(lut^T)
__device__ __half g_emb[Bq * Wq * Eq];            // half embeddings
__device__ float g_xg[2 * (size_t)Bq * Wq * G4];  // per-dir input projections (f32)
__device__ float g_hseq[Bq * Wq * 2 * Hq];        // layer-1 output (f32, for gather)
__device__ __half g_hseq_h[Bq * Wq * 2 * Hq];     // layer-0 output (half, feeds proj-1)
__device__ __half g_ha[2][2 * Bq * Hq];           // h ping-pong (half, GEMM A)
__device__ float g_c[2 * Bq * Hq];
__device__ __half g_wr[10485760];                 // half weights: wih0|whh0|wih1|whh1
__device__ unsigned g_gbar[2 * 16 * Wq];          // group barriers [layer][group][step]

#define OFF_WIH0 0
#define OFF_WHH0 2097152
#define OFF_WIH1 4194304
#define OFF_WHH1 8388608
#define W_TOTAL  10485760

__device__ __forceinline__ float sig_fast(float x) {
    return __fdividef(1.0f, 1.0f + __expf(-x));
}
__device__ __forceinline__ float tanh_fast(float x) {
    return 2.0f * __fdividef(1.0f, 1.0f + __expf(-2.0f * x)) - 1.0f;
}
__device__ __forceinline__ void cp16(uint32_t dst, const void* src) {
    asm volatile("cp.async.cg.shared.global [%0], [%1], 16;" :: "r"(dst), "l"(src));
}
#define LDSM_X4(r0, r1, r2, r3, addr) \
    asm volatile("ldmatrix.sync.aligned.m8n8.x4.shared.b16 {%0,%1,%2,%3}, [%4];" \
                 : "=r"(r0), "=r"(r1), "=r"(r2), "=r"(r3) : "r"(addr))

// ---------------- one-time: all weights -> half, zero barriers (fused) ----------
__global__ void cvt_all_weights_kernel(const float* __restrict__ w0, const float* __restrict__ w1,
                                       const float* __restrict__ w2, const float* __restrict__ w3) {
    int i = blockIdx.x * blockDim.x + threadIdx.x;     // one thread = 4 floats
    if (i < 2 * 16 * Wq) g_gbar[i] = 0;
    int idx4 = i * 4;
    if (idx4 >= W_TOTAL) return;
    const float* src; int off;
    if (idx4 < OFF_WHH0)      { src = w0; off = idx4; }
    else if (idx4 < OFF_WIH1) { src = w1; off = idx4 - OFF_WHH0; }
    else if (idx4 < OFF_WHH1) { src = w2; off = idx4 - OFF_WIH1; }
    else                      { src = w3; off = idx4 - OFF_WHH1; }
    float4 v = *(const float4*)(src + off);
    __half2 a = __floats2half2_rn(v.x, v.y);
    __half2 b = __floats2half2_rn(v.z, v.w);
    __half2* dst = (__half2*)&g_wr[idx4];
    dst[0] = a; dst[1] = b;
}

// ---------------- tanh + transpose lookup: g_table[v][e] = h(tanh(lut[e][v])) ----
__global__ void tanh_transpose_kernel(const float* __restrict__ lut) {
    __shared__ float tile[32][33];
    int v0 = blockIdx.x * 32;
    int e0 = blockIdx.y * 32;
    int tx = threadIdx.x, ty = threadIdx.y;
#pragma unroll
    for (int i = ty; i < 32; i += 8) {
        int e = e0 + i, v = v0 + tx;
        tile[i][tx] = (v < Vq) ? lut[(size_t)e * Vq + v] : 0.0f;
    }
    __syncthreads();
#pragma unroll
    for (int i = ty; i < 32; i += 8) {
        int v = v0 + i, e = e0 + tx;
        if (v < Vq) g_table[(size_t)v * Eq + e] = __float2half_rn(tanhf(tile[tx][i]));
    }
}

// ---------------- embedding gather (u32 granularity = 2 halves) ----------------
__global__ void embed_kernel(const int* __restrict__ ques) {
    int idx = blockIdx.x * blockDim.x + threadIdx.x;   // over u32s
    if (idx >= Bq * Wq * Eq / 2) return;
    int e2 = idx & 255;
    int bw = idx >> 8;
    int v = ques[bw];
    uint32_t val = 0;
    if (v > 0) val = ((const uint32_t*)g_table)[(size_t)(v - 1) * 256 + e2];
    ((uint32_t*)g_emb)[idx] = val;
}

// ---------------- FP16 tensor-core NT GEMM, 4-stage cp.async + ldmatrix --------
#define P_ASZ (128 * 20)            // u32 per stage
#define P_SMEM (4 * P_ASZ * 2 * 4)  // 81920 B
template <int HAS_BIAS>
__global__ __launch_bounds__(256, 2) void gemm_hf(
    const __half* __restrict__ A, size_t aDirStride,
    const __half* __restrict__ Bw, size_t bDirStride,
    const float* __restrict__ bias,
    float* __restrict__ C, size_t cDirStride,
    int M, int N, int K)
{
    extern __shared__ uint32_t sm[];
    uint32_t* smA = sm;                 // [4][128][20]
    uint32_t* smB = sm + 4 * P_ASZ;
    uint32_t baseA = (uint32_t)__cvta_generic_to_shared(smA);
    uint32_t baseB = (uint32_t)__cvta_generic_to_shared(smB);

    int dir = blockIdx.z;
    A  += (size_t)dir * aDirStride;
    Bw += (size_t)dir * bDirStride;
    C  += (size_t)dir * cDirStride;

    int m0 = blockIdx.y * 128;
    int n0 = blockIdx.x * 128;
    int tid = threadIdx.x;
    int wid = tid >> 5, lane = tid & 31;
    int wm = wid >> 2, wn = wid & 3;
    int gid = lane >> 2, tg = lane & 3;

    // ldmatrix per-lane geometry
    int lrow = (lane & 7) + ((lane >> 3) & 1) * 8;   // row within 16-row tile
    int lk = (lane >> 4) * 4;                        // u32 k-offset (k-hi half)
    uint32_t aAddr = baseA + (uint32_t)(((wm * 64 + lrow) * 20 + lk) * 4);
    uint32_t bAddr = baseB + (uint32_t)(((wn * 32 + lrow) * 20 + lk) * 4);

    float acc[4][4][4];
#pragma unroll
    for (int mt = 0; mt < 4; mt++)
#pragma unroll
        for (int nt = 0; nt < 4; nt++)
#pragma unroll
            for (int r = 0; r < 4; r++) acc[mt][nt][r] = 0.0f;

    int niter = K >> 5;                 // BK = 32 halves

    auto load_stage = [&](int s, int k0) {
#pragma unroll
        for (int i = 0; i < 2; i++) {
            int c = tid + i * 256;
            int row = c >> 2, seg = c & 3;
            cp16(baseA + (s * P_ASZ + row * 20 + seg * 4) * 4,
                 A + (size_t)(m0 + row) * K + k0 + seg * 8);
            cp16(baseB + (s * P_ASZ + row * 20 + seg * 4) * 4,
                 Bw + (size_t)(n0 + row) * K + k0 + seg * 8);
        }
        asm volatile("cp.async.commit_group;");
    };

    load_stage(0, 0);
    load_stage(1, 32);
    load_stage(2, 64);

    for (int it = 0; it < niter; it++) {
        int rem = niter - 1 - it;
        if (rem >= 2)      asm volatile("cp.async.wait_group 2;");
        else if (rem == 1) asm volatile("cp.async.wait_group 1;");
        else               asm volatile("cp.async.wait_group 0;");
        __syncthreads();
        if (it + 3 < niter) load_stage((it + 3) & 3, (it + 3) * 32);

        uint32_t sofs = (uint32_t)((it & 3) * P_ASZ * 4);
#pragma unroll
        for (int g = 0; g < 2; g++) {
            uint32_t kby = g * 32;                   // 8 u32 = 32 B
            uint32_t af[4][4], bf[4][2];
#pragma unroll
            for (int mt = 0; mt < 4; mt++)
                LDSM_X4(af[mt][0], af[mt][1], af[mt][2], af[mt][3],
                        aAddr + sofs + (uint32_t)(mt * 16 * 20 * 4) + kby);
#pragma unroll
            for (int p = 0; p < 2; p++)
                LDSM_X4(bf[2 * p][0], bf[2 * p + 1][0], bf[2 * p][1], bf[2 * p + 1][1],
                        bAddr + sofs + (uint32_t)(p * 16 * 20 * 4) + kby);
#pragma unroll
            for (int mt = 0; mt < 4; mt++)
#pragma unroll
                for (int nt = 0; nt < 4; nt++) {
                    asm volatile(
                        "mma.sync.aligned.m16n8k16.row.col.f32.f16.f16.f32 "
                        "{%0,%1,%2,%3}, {%4,%5,%6,%7}, {%8,%9}, {%0,%1,%2,%3};"
                        : "+f"(acc[mt][nt][0]), "+f"(acc[mt][nt][1]),
                          "+f"(acc[mt][nt][2]), "+f"(acc[mt][nt][3])
                        : "r"(af[mt][0]), "r"(af[mt][1]), "r"(af[mt][2]), "r"(af[mt][3]),
                          "r"(bf[nt][0]), "r"(bf[nt][1]));
                }
        }
    }

    const float* bp = bias + (size_t)dir * 2 * G4;
#pragma unroll
    for (int mt = 0; mt < 4; mt++) {
#pragma unroll
        for (int nt = 0; nt < 4; nt++) {
            int m = m0 + wm * 64 + mt * 16 + gid;
            int n = n0 + wn * 32 + nt * 8 + tg * 2;
            float2 v0, v1;
            v0.x = acc[mt][nt][0]; v0.y = acc[mt][nt][1];
            v1.x = acc[mt][nt][2]; v1.y = acc[mt][nt][3];
            if (HAS_BIAS) {
                float bx = bp[n] + bp[G4 + n];
                float by = bp[n + 1] + bp[G4 + n + 1];
                v0.x += bx; v0.y += by; v1.x += bx; v1.y += by;
            }
            *(float2*)(C + (size_t)m * N + n) = v0;
            *(float2*)(C + (size_t)(m + 8) * N + n) = v1;
        }
    }
}

// ---------------- persistent fused LSTM recurrence (fp16 mma + ldmatrix) -------
// Group-local barriers: group = bx>>3 = (dir, m0); only the 8 CTAs producing
// this group's h sync together. B0..B2 prefetched across the barrier.
#define R_ASZ (64 * 36)         // u32 per A stage
#define R_BSZ (256 * 36)        // u32 per B stage
#define R_GSM (3 * (R_ASZ + R_BSZ))          // u32 offset of gate staging
#define R_SMEM ((R_GSM + 64 * 258) * 4)      // 204288 B
#define GSM_STRIDE 258
template <int LAYER0>
__global__ __launch_bounds__(256) void lstm_persist(
    const __half* __restrict__ whh,      // [2 dirs][G4][Hq] half
    const float* __restrict__ xg,        // [2 dirs][Bq][Wq][G4] f32
    int bar_ofs)
{
    extern __shared__ uint32_t sm[];
    uint32_t* smA = sm;                   // [3][64][36]
    uint32_t* smB = sm + 3 * R_ASZ;       // [3][256][36]
    float* gsm = (float*)(sm + R_GSM);    // [64][258] dedicated
    uint32_t baseA = (uint32_t)__cvta_generic_to_shared(smA);
    uint32_t baseB = (uint32_t)__cvta_generic_to_shared(smB);

    int tid = threadIdx.x;
    int bx = blockIdx.x;
    int dir = bx >> 6;
    int r = bx & 63;
    int m0 = (r >> 3) * 64;
    int ht0 = (r & 7) * 64;
    int grp = bx >> 3;                    // (dir, m0) group of 8 CTAs

    int wid = tid >> 5, lane = tid & 31;
    int wm = wid >> 2, wn = wid & 3;      // warp tile: 32 m x 64 n
    int gid = lane >> 2, tg = lane & 3;

    // ldmatrix per-lane geometry
    int lrow = (lane & 7) + ((lane >> 3) & 1) * 8;
    int lk = (lane >> 4) * 4;
    uint32_t aAddr = baseA + (uint32_t)(((wm * 32 + lrow) * 36 + lk) * 4);
    uint32_t bAddr = baseB + (uint32_t)(((wn * 16 + lrow) * 36 + lk) * 4);

    const __half* wbase = whh + (size_t)dir * G4 * Hq;
    const float* xgd = xg + (size_t)dir * Bq * Wq * G4;

    auto load_A = [&](int s, int k0, const __half* habase) {
#pragma unroll
        for (int i = 0; i < 2; i++) {
            int c = tid + i * 256;
            int row = c >> 3, seg = c & 7;
            cp16(baseA + (s * R_ASZ + row * 36 + seg * 4) * 4,
                 habase + (size_t)(m0 + row) * Hq + k0 + seg * 8);
        }
        asm volatile("cp.async.commit_group;");
    };
    auto load_B = [&](int s, int k0) {
#pragma unroll
        for (int i = 0; i < 8; i++) {
            int c = tid + i * 256;
            int row = c >> 3, seg = c & 7;
            int grow = ((row >> 6) << 9) + ht0 + (row & 63);
            cp16(baseB + (s * R_BSZ + row * 36 + seg * 4) * 4,
                 wbase + (size_t)grow * Hq + k0 + seg * 8);
        }
        asm volatile("cp.async.commit_group;");
    };
    auto load_AB = [&](int s, int k0, const __half* habase) {
#pragma unroll
        for (int i = 0; i < 2; i++) {
            int c = tid + i * 256;
            int row = c >> 3, seg = c & 7;
            cp16(baseA + (s * R_ASZ + row * 36 + seg * 4) * 4,
                 habase + (size_t)(m0 + row) * Hq + k0 + seg * 8);
        }
#pragma unroll
        for (int i = 0; i < 8; i++) {
            int c = tid + i * 256;
            int row = c >> 3, seg = c & 7;
            int grow = ((row >> 6) << 9) + ht0 + (row & 63);
            cp16(baseB + (s * R_BSZ + row * 36 + seg * 4) * 4,
                 wbase + (size_t)grow * Hq + k0 + seg * 8);
        }
        asm volatile("cp.async.commit_group;");
    };

    for (int step = 0; step < Wq; step++) {
        int t_ = dir ? (Wq - 1 - step) : step;

        // L2-prefetch this step's xg slice (consumed in the epilogue)
        {
#pragma unroll
            for (int i = 0; i < 2; i++) {
                int c = tid + i * 256;            // 0..511 lines
                int row = c >> 3, seg = c & 7;
                const float* p = xgd + ((size_t)(m0 + row) * Wq + t_) * G4
                                 + (seg >> 1) * 512 + ht0 + (seg & 1) * 32;
                asm volatile("prefetch.global.L2 [%0];" :: "l"(p));
            }
        }

        float acc[2][8][4];
#pragma unroll
        for (int mt = 0; mt < 2; mt++)
#pragma unroll
            for (int t = 0; t < 8; t++)
#pragma unroll
                for (int q = 0; q < 4; q++) acc[mt][t][q] = 0.0f;

        if (step > 0) {
            const __half* habase = g_ha[(step - 1) & 1] + dir * Bq * Hq;
            // B0,B1,B2 already in flight (prefetched before the group barrier).
            load_A(0, 0, habase);
            load_A(1, 64, habase);

            for (int kc = 0; kc < 8; kc++) {       // BK = 64 halves, stages kc%3
                if (kc < 7) asm volatile("cp.async.wait_group 1;");
                else        asm volatile("cp.async.wait_group 0;");
                __syncthreads();
                if (kc == 0)      load_A(2, 128, habase);          // B2 resident
                else if (kc <= 5) load_AB((kc + 2) % 3, (kc + 2) * 64, habase);

                uint32_t sa = (uint32_t)((kc % 3) * R_ASZ * 4);
                uint32_t sb = (uint32_t)((kc % 3) * R_BSZ * 4);
#pragma unroll
                for (int g = 0; g < 4; g++) {
                    uint32_t kby = g * 32;
                    uint32_t af[2][4], bf[8][2];
#pragma unroll
                    for (int mt = 0; mt < 2; mt++)
                        LDSM_X4(af[mt][0], af[mt][1], af[mt][2], af[mt][3],
                                aAddr + sa + (uint32_t)(mt * 16 * 36 * 4) + kby);
#pragma unroll
                    for (int p = 0; p < 4; p++)
                        LDSM_X4(bf[2 * p][0], bf[2 * p + 1][0], bf[2 * p][1], bf[2 * p + 1][1],
                                bAddr + sb + (uint32_t)(p * 64 * 36 * 4) + kby);
#pragma unroll
                    for (int mt = 0; mt < 2; mt++)
#pragma unroll
                        for (int t = 0; t < 8; t++) {
                            asm volatile(
                                "mma.sync.aligned.m16n8k16.row.col.f32.f16.f16.f32 "
                                "{%0,%1,%2,%3}, {%4,%5,%6,%7}, {%8,%9}, {%0,%1,%2,%3};"
                                : "+f"(acc[mt][t][0]), "+f"(acc[mt][t][1]),
                                  "+f"(acc[mt][t][2]), "+f"(acc[mt][t][3])
                                : "r"(af[mt][0]), "r"(af[mt][1]), "r"(af[mt][2]), "r"(af[mt][3]),
                                  "r"(bf[t][0]), "r"(bf[t][1]));
                        }
                }
            }
        }

        // all stages consumed; prefetch next step's weight chunks across the barrier
        __syncthreads();
        if (step < Wq - 1) {
            load_B(0, 0);
            load_B(1, 64);
            load_B(2, 128);
        }

        // ---- stage gates into dedicated smem ----
#pragma unroll
        for (int mt = 0; mt < 2; mt++)
#pragma unroll
            for (int t = 0; t < 8; t++)
#pragma unroll
                for (int rs = 0; rs < 2; rs++) {
                    int mr = wm * 32 + mt * 16 + gid + rs * 8;
                    int nc = ((t >> 1) << 6) + wn * 16 + ((t & 1) << 3) + tg * 2;
                    float2 v;
                    v.x = acc[mt][t][rs * 2];
                    v.y = acc[mt][t][rs * 2 + 1];
                    *(float2*)&gsm[mr * GSM_STRIDE + nc] = v;
                }
        __syncthreads();

        // ---- coalesced fused gate epilogue ----
        __half* haw = g_ha[step & 1] + dir * Bq * Hq;
        int hl = (tid & 31) * 2;
        int mb = tid >> 5;
#pragma unroll
        for (int mm = 0; mm < 8; mm++) {
            int m = mb + mm * 8;
            int gm = m0 + m;
            const float* gr = &gsm[m * GSM_STRIDE];
            const float* xp = xgd + ((size_t)gm * Wq + t_) * G4 + ht0 + hl;
            float2 gi = *(const float2*)&gr[hl];
            float2 gf = *(const float2*)&gr[64 + hl];
            float2 gg = *(const float2*)&gr[128 + hl];
            float2 go = *(const float2*)&gr[192 + hl];
            float2 xi = *(const float2*)&xp[0];
            float2 xf = *(const float2*)&xp[512];
            float2 xgg = *(const float2*)&xp[1024];
            float2 xo = *(const float2*)&xp[1536];
            int ci = dir * Bq * Hq + gm * Hq + ht0 + hl;
            float2 cprev = (step == 0) ? make_float2(0.f, 0.f) : *(const float2*)&g_c[ci];
            float2 cv, hv;
            cv.x = sig_fast(gf.x + xf.x) * cprev.x + sig_fast(gi.x + xi.x) * tanh_fast(gg.x + xgg.x);
            cv.y = sig_fast(gf.y + xf.y) * cprev.y + sig_fast(gi.y + xi.y) * tanh_fast(gg.y + xgg.y);
            hv.x = sig_fast(go.x + xo.x) * tanh_fast(cv.x);
            hv.y = sig_fast(go.y + xo.y) * tanh_fast(cv.y);
            *(float2*)&g_c[ci] = cv;
            __half2 hh = __floats2half2_rn(hv.x, hv.y);
            *(__half2*)&haw[gm * Hq + ht0 + hl] = hh;
            size_t so = ((size_t)gm * Wq + t_) * (2 * Hq) + dir * Hq + ht0 + hl;
            if (LAYER0) {
                *(__half2*)&g_hseq_h[so] = hh;
            } else {
                *(float2*)&g_hseq[so] = hv;
            }
        }

        // ---- group-local barrier (8 CTAs sharing (dir, m0)) ----
        if (step < Wq - 1) {
            __threadfence();
            __syncthreads();
            if (tid == 0) {
                unsigned* ctr = &g_gbar[bar_ofs + grp * Wq + step];
                atomicAdd(ctr, 1u);
                unsigned v;
                do {
                    asm volatile("ld.acquire.gpu.u32 %0, [%1];"
                                 : "=r"(v) : "l"(ctr) : "memory");
                    if (v < 8u) __nanosleep(32);
                } while (v < 8u);
            }
            __syncthreads();
        }
    }
}

// ---------------- final gather at t = len-1 ----------------
__global__ void gather_kernel(const int* __restrict__ qlen, float* __restrict__ out) {
    int idx = blockIdx.x * blockDim.x + threadIdx.x;
    if (idx >= Bq * 2 * Hq) return;
    int b = idx / (2 * Hq);
    int j = idx - b * (2 * Hq);
    int t = qlen[b] - 1;
    out[idx] = g_hseq[((size_t)b * Wq + t) * (2 * Hq) + j];
}

// ---------------- launch ----------------
extern "C" void kernel_launch(void* const* d_in, const int* in_sizes, int n_in,
                              void* d_out, int out_size)
{
    const int*   ques = (const int*)d_in[0];
    const int*   qlen = (const int*)d_in[1];
    const float* lut  = (const float*)d_in[2];
    const float* wih0 = (const float*)d_in[3];
    const float* whh0 = (const float*)d_in[4];
    const float* b0   = (const float*)d_in[5];
    const float* wih1 = (const float*)d_in[6];
    const float* whh1 = (const float*)d_in[7];
    const float* b1   = (const float*)d_in[8];
    float* out = (float*)d_out;

    __half *emb, *hseq_h, *wr;
    float *xg;
    cudaGetSymbolAddress((void**)&emb,    g_emb);
    cudaGetSymbolAddress((void**)&xg,     g_xg);
    cudaGetSymbolAddress((void**)&hseq_h, g_hseq_h);
    cudaGetSymbolAddress((void**)&wr,     g_wr);

    cudaFuncSetAttribute(gemm_hf<1>, cudaFuncAttributeMaxDynamicSharedMemorySize, P_SMEM);
    cudaFuncSetAttribute(lstm_persist<0>, cudaFuncAttributeMaxDynamicSharedMemorySize, R_SMEM);
    cudaFuncSetAttribute(lstm_persist<1>, cudaFuncAttributeMaxDynamicSharedMemorySize, R_SMEM);

    // 0) fused: all weights -> half + barrier zeroing; table build
    cvt_all_weights_kernel<<<(W_TOTAL / 4 + 255) / 256, 256>>>(wih0, whh0, wih1, whh1);
    {
        dim3 grid((Vq + 31) / 32, Eq / 32);
        tanh_transpose_kernel<<<grid, dim3(32, 8)>>>(lut);
    }

    // 1) embedding
    embed_kernel<<<(Bq * Wq * Eq / 2 + 255) / 256, 256>>>(ques);

    // 2) layer-0 input projection (fp16 mma)
    {
        dim3 grid(G4 / 128, (Bq * Wq) / 128, 2);
        gemm_hf<1><<<grid, 256, P_SMEM>>>(emb, 0,
                                          wr + OFF_WIH0, (size_t)G4 * Eq,
                                          b0,
                                          xg, (size_t)Bq * Wq * G4,
                                          Bq * Wq, G4, Eq);
    }

    // 3) layer-0 recurrence (writes half hseq)
    lstm_persist<1><<<NCTA, 256, R_SMEM>>>(wr + OFF_WHH0, xg, 0);

    // 4) layer-1 input projection (K = 2H, A = half hseq)
    {
        dim3 grid(G4 / 128, (Bq * Wq) / 128, 2);
        gemm_hf<1><<<grid, 256, P_SMEM>>>(hseq_h, 0,
                                          wr + OFF_WIH1, (size_t)G4 * 2 * Hq,
                                          b1,
                                          xg, (size_t)Bq * Wq * G4,
                                          Bq * Wq, G4, 2 * Hq);
    }

    // 5) layer-1 recurrence (writes f32 hseq for gather)
    lstm_persist<0><<<NCTA, 256, R_SMEM>>>(wr + OFF_WHH1, xg, 16 * Wq);

    // 6) gather
    gather_kernel<<<(Bq * 2 * Hq + 255) / 256, 256>>>(qlen, out);
}

// round 13
// speedup vs baseline: 1.7287x; 1.0173x over previous
#include <cuda_runtime.h>
#include <cuda_fp16.h>
#include <math.h>
#include <stdint.h>

#define Bq 512
#define Wq 40
#define Vq 12000
#define Eq 512
#define Hq 512
#define G4 2048   // 4*H
#define NCTA 128

// ---------------- scratch (device globals; no allocation) ----------------
__device__ __half g_table[(size_t)Vq * Eq];       // half tanh(lut^T)
__device__ __half g_emb[Bq * Wq * Eq];            // half embeddings
__device__ __half g_xg[2 * (size_t)Bq * Wq * G4]; // per-dir input projections (half)
__device__ float g_hseq[Bq * Wq * 2 * Hq];        // layer-1 output (f32, for gather)
__device__ __half g_hseq_h[Bq * Wq * 2 * Hq];     // layer-0 output (half, feeds proj-1)
__device__ __half g_ha[2][2 * Bq * Hq];           // h ping-pong (half, GEMM A)
__device__ float g_c[2 * Bq * Hq];
__device__ __half g_wr[10485760];                 // half weights: wih0|whh0|wih1|whh1
__device__ unsigned g_gbar[2 * 16 * Wq];          // group barriers [layer][group][step]

#define OFF_WIH0 0
#define OFF_WHH0 2097152
#define OFF_WIH1 4194304
#define OFF_WHH1 8388608
#define W_TOTAL  10485760

__device__ __forceinline__ float sig_fast(float x) {
    return __fdividef(1.0f, 1.0f + __expf(-x));
}
__device__ __forceinline__ float tanh_fast(float x) {
    return 2.0f * __fdividef(1.0f, 1.0f + __expf(-2.0f * x)) - 1.0f;
}
__device__ __forceinline__ void cp16(uint32_t dst, const void* src) {
    asm volatile("cp.async.cg.shared.global [%0], [%1], 16;" :: "r"(dst), "l"(src));
}
#define LDSM_X4(r0, r1, r2, r3, addr) \
    asm volatile("ldmatrix.sync.aligned.m8n8.x4.shared.b16 {%0,%1,%2,%3}, [%4];" \
                 : "=r"(r0), "=r"(r1), "=r"(r2), "=r"(r3) : "r"(addr))

// ---------------- one-time: all weights -> half, zero barriers (fused) ----------
__global__ void cvt_all_weights_kernel(const float* __restrict__ w0, const float* __restrict__ w1,
                                       const float* __restrict__ w2, const float* __restrict__ w3) {
    int i = blockIdx.x * blockDim.x + threadIdx.x;     // one thread = 4 floats
    if (i < 2 * 16 * Wq) g_gbar[i] = 0;
    int idx4 = i * 4;
    if (idx4 >= W_TOTAL) return;
    const float* src; int off;
    if (idx4 < OFF_WHH0)      { src = w0; off = idx4; }
    else if (idx4 < OFF_WIH1) { src = w1; off = idx4 - OFF_WHH0; }
    else if (idx4 < OFF_WHH1) { src = w2; off = idx4 - OFF_WIH1; }
    else                      { src = w3; off = idx4 - OFF_WHH1; }
    float4 v = *(const float4*)(src + off);
    __half2 a = __floats2half2_rn(v.x, v.y);
    __half2 b = __floats2half2_rn(v.z, v.w);
    __half2* dst = (__half2*)&g_wr[idx4];
    dst[0] = a; dst[1] = b;
}

// ---------------- tanh + transpose lookup: g_table[v][e] = h(tanh(lut[e][v])) ----
__global__ void tanh_transpose_kernel(const float* __restrict__ lut) {
    __shared__ float tile[32][33];
    int v0 = blockIdx.x * 32;
    int e0 = blockIdx.y * 32;
    int tx = threadIdx.x, ty = threadIdx.y;
#pragma unroll
    for (int i = ty; i < 32; i += 8) {
        int e = e0 + i, v = v0 + tx;
        tile[i][tx] = (v < Vq) ? lut[(size_t)e * Vq + v] : 0.0f;
    }
    __syncthreads();
#pragma unroll
    for (int i = ty; i < 32; i += 8) {
        int v = v0 + i, e = e0 + tx;
        if (v < Vq) g_table[(size_t)v * Eq + e] = __float2half_rn(tanhf(tile[tx][i]));
    }
}

// ---------------- embedding gather (u32 granularity = 2 halves) ----------------
__global__ void embed_kernel(const int* __restrict__ ques) {
    int idx = blockIdx.x * blockDim.x + threadIdx.x;   // over u32s
    if (idx >= Bq * Wq * Eq / 2) return;
    int e2 = idx & 255;
    int bw = idx >> 8;
    int v = ques[bw];
    uint32_t val = 0;
    if (v > 0) val = ((const uint32_t*)g_table)[(size_t)(v - 1) * 256 + e2];
    ((uint32_t*)g_emb)[idx] = val;
}

// ---------------- FP16 tensor-core NT GEMM, 4-stage cp.async + ldmatrix --------
// Output written as HALF (gate pre-activations; |v| ~ 1-2).
#define P_ASZ (128 * 20)            // u32 per stage
#define P_SMEM (4 * P_ASZ * 2 * 4)  // 81920 B
template <int HAS_BIAS>
__global__ __launch_bounds__(256, 2) void gemm_hf(
    const __half* __restrict__ A, size_t aDirStride,
    const __half* __restrict__ Bw, size_t bDirStride,
    const float* __restrict__ bias,
    __half* __restrict__ C, size_t cDirStride,
    int M, int N, int K)
{
    extern __shared__ uint32_t sm[];
    uint32_t* smA = sm;                 // [4][128][20]
    uint32_t* smB = sm + 4 * P_ASZ;
    uint32_t baseA = (uint32_t)__cvta_generic_to_shared(smA);
    uint32_t baseB = (uint32_t)__cvta_generic_to_shared(smB);

    int dir = blockIdx.z;
    A  += (size_t)dir * aDirStride;
    Bw += (size_t)dir * bDirStride;
    C  += (size_t)dir * cDirStride;

    int m0 = blockIdx.y * 128;
    int n0 = blockIdx.x * 128;
    int tid = threadIdx.x;
    int wid = tid >> 5, lane = tid & 31;
    int wm = wid >> 2, wn = wid & 3;
    int gid = lane >> 2, tg = lane & 3;

    // ldmatrix per-lane geometry
    int lrow = (lane & 7) + ((lane >> 3) & 1) * 8;
    int lk = (lane >> 4) * 4;
    uint32_t aAddr = baseA + (uint32_t)(((wm * 64 + lrow) * 20 + lk) * 4);
    uint32_t bAddr = baseB + (uint32_t)(((wn * 32 + lrow) * 20 + lk) * 4);

    float acc[4][4][4];
#pragma unroll
    for (int mt = 0; mt < 4; mt++)
#pragma unroll
        for (int nt = 0; nt < 4; nt++)
#pragma unroll
            for (int r = 0; r < 4; r++) acc[mt][nt][r] = 0.0f;

    int niter = K >> 5;                 // BK = 32 halves

    auto load_stage = [&](int s, int k0) {
#pragma unroll
        for (int i = 0; i < 2; i++) {
            int c = tid + i * 256;
            int row = c >> 2, seg = c & 3;
            cp16(baseA + (s * P_ASZ + row * 20 + seg * 4) * 4,
                 A + (size_t)(m0 + row) * K + k0 + seg * 8);
            cp16(baseB + (s * P_ASZ + row * 20 + seg * 4) * 4,
                 Bw + (size_t)(n0 + row) * K + k0 + seg * 8);
        }
        asm volatile("cp.async.commit_group;");
    };

    load_stage(0, 0);
    load_stage(1, 32);
    load_stage(2, 64);

    for (int it = 0; it < niter; it++) {
        int rem = niter - 1 - it;
        if (rem >= 2)      asm volatile("cp.async.wait_group 2;");
        else if (rem == 1) asm volatile("cp.async.wait_group 1;");
        else               asm volatile("cp.async.wait_group 0;");
        __syncthreads();
        if (it + 3 < niter) load_stage((it + 3) & 3, (it + 3) * 32);

        uint32_t sofs = (uint32_t)((it & 3) * P_ASZ * 4);
#pragma unroll
        for (int g = 0; g < 2; g++) {
            uint32_t kby = g * 32;
            uint32_t af[4][4], bf[4][2];
#pragma unroll
            for (int mt = 0; mt < 4; mt++)
                LDSM_X4(af[mt][0], af[mt][1], af[mt][2], af[mt][3],
                        aAddr + sofs + (uint32_t)(mt * 16 * 20 * 4) + kby);
#pragma unroll
            for (int p = 0; p < 2; p++)
                LDSM_X4(bf[2 * p][0], bf[2 * p + 1][0], bf[2 * p][1], bf[2 * p + 1][1],
                        bAddr + sofs + (uint32_t)(p * 16 * 20 * 4) + kby);
#pragma unroll
            for (int mt = 0; mt < 4; mt++)
#pragma unroll
                for (int nt = 0; nt < 4; nt++) {
                    asm volatile(
                        "mma.sync.aligned.m16n8k16.row.col.f32.f16.f16.f32 "
                        "{%0,%1,%2,%3}, {%4,%5,%6,%7}, {%8,%9}, {%0,%1,%2,%3};"
                        : "+f"(acc[mt][nt][0]), "+f"(acc[mt][nt][1]),
                          "+f"(acc[mt][nt][2]), "+f"(acc[mt][nt][3])
                        : "r"(af[mt][0]), "r"(af[mt][1]), "r"(af[mt][2]), "r"(af[mt][3]),
                          "r"(bf[nt][0]), "r"(bf[nt][1]));
                }
        }
    }

    const float* bp = bias + (size_t)dir * 2 * G4;
#pragma unroll
    for (int mt = 0; mt < 4; mt++) {
#pragma unroll
        for (int nt = 0; nt < 4; nt++) {
            int m = m0 + wm * 64 + mt * 16 + gid;
            int n = n0 + wn * 32 + nt * 8 + tg * 2;
            float2 v0, v1;
            v0.x = acc[mt][nt][0]; v0.y = acc[mt][nt][1];
            v1.x = acc[mt][nt][2]; v1.y = acc[mt][nt][3];
            if (HAS_BIAS) {
                float bx = bp[n] + bp[G4 + n];
                float by = bp[n + 1] + bp[G4 + n + 1];
                v0.x += bx; v0.y += by; v1.x += bx; v1.y += by;
            }
            *(__half2*)(C + (size_t)m * N + n) = __floats2half2_rn(v0.x, v0.y);
            *(__half2*)(C + (size_t)(m + 8) * N + n) = __floats2half2_rn(v1.x, v1.y);
        }
    }
}

// ---------------- persistent fused LSTM recurrence (fp16 mma + ldmatrix) -------
// Group-local barriers (8 CTAs sharing (dir, m0)); B0..B2 prefetched across
// the barrier; xg read as half.
#define R_ASZ (64 * 36)         // u32 per A stage
#define R_BSZ (256 * 36)        // u32 per B stage
#define R_GSM (3 * (R_ASZ + R_BSZ))          // u32 offset of gate staging
#define R_SMEM ((R_GSM + 64 * 258) * 4)      // 204288 B
#define GSM_STRIDE 258
template <int LAYER0>
__global__ __launch_bounds__(256) void lstm_persist(
    const __half* __restrict__ whh,      // [2 dirs][G4][Hq] half
    const __half* __restrict__ xg,       // [2 dirs][Bq][Wq][G4] half
    int bar_ofs)
{
    extern __shared__ uint32_t sm[];
    uint32_t* smA = sm;                   // [3][64][36]
    uint32_t* smB = sm + 3 * R_ASZ;       // [3][256][36]
    float* gsm = (float*)(sm + R_GSM);    // [64][258] dedicated
    uint32_t baseA = (uint32_t)__cvta_generic_to_shared(smA);
    uint32_t baseB = (uint32_t)__cvta_generic_to_shared(smB);

    int tid = threadIdx.x;
    int bx = blockIdx.x;
    int dir = bx >> 6;
    int r = bx & 63;
    int m0 = (r >> 3) * 64;
    int ht0 = (r & 7) * 64;
    int grp = bx >> 3;                    // (dir, m0) group of 8 CTAs

    int wid = tid >> 5, lane = tid & 31;
    int wm = wid >> 2, wn = wid & 3;      // warp tile: 32 m x 64 n
    int gid = lane >> 2, tg = lane & 3;

    // ldmatrix per-lane geometry
    int lrow = (lane & 7) + ((lane >> 3) & 1) * 8;
    int lk = (lane >> 4) * 4;
    uint32_t aAddr = baseA + (uint32_t)(((wm * 32 + lrow) * 36 + lk) * 4);
    uint32_t bAddr = baseB + (uint32_t)(((wn * 16 + lrow) * 36 + lk) * 4);

    const __half* wbase = whh + (size_t)dir * G4 * Hq;
    const __half* xgd = xg + (size_t)dir * Bq * Wq * G4;

    auto load_A = [&](int s, int k0, const __half* habase) {
#pragma unroll
        for (int i = 0; i < 2; i++) {
            int c = tid + i * 256;
            int row = c >> 3, seg = c & 7;
            cp16(baseA + (s * R_ASZ + row * 36 + seg * 4) * 4,
                 habase + (size_t)(m0 + row) * Hq + k0 + seg * 8);
        }
        asm volatile("cp.async.commit_group;");
    };
    auto load_B = [&](int s, int k0) {
#pragma unroll
        for (int i = 0; i < 8; i++) {
            int c = tid + i * 256;
            int row = c >> 3, seg = c & 7;
            int grow = ((row >> 6) << 9) + ht0 + (row & 63);
            cp16(baseB + (s * R_BSZ + row * 36 + seg * 4) * 4,
                 wbase + (size_t)grow * Hq + k0 + seg * 8);
        }
        asm volatile("cp.async.commit_group;");
    };
    auto load_AB = [&](int s, int k0, const __half* habase) {
#pragma unroll
        for (int i = 0; i < 2; i++) {
            int c = tid + i * 256;
            int row = c >> 3, seg = c & 7;
            cp16(baseA + (s * R_ASZ + row * 36 + seg * 4) * 4,
                 habase + (size_t)(m0 + row) * Hq + k0 + seg * 8);
        }
#pragma unroll
        for (int i = 0; i < 8; i++) {
            int c = tid + i * 256;
            int row = c >> 3, seg = c & 7;
            int grow = ((row >> 6) << 9) + ht0 + (row & 63);
            cp16(baseB + (s * R_BSZ + row * 36 + seg * 4) * 4,
                 wbase + (size_t)grow * Hq + k0 + seg * 8);
        }
        asm volatile("cp.async.commit_group;");
    };

    for (int step = 0; step < Wq; step++) {
        int t_ = dir ? (Wq - 1 - step) : step;

        // L2-prefetch this step's xg slice: 64 rows x 4 gate segs x 128B lines
        if (tid < 256) {
            int row = tid >> 2, seg = tid & 3;
            const __half* p = xgd + ((size_t)(m0 + row) * Wq + t_) * G4
                              + seg * 512 + ht0;
            asm volatile("prefetch.global.L2 [%0];" :: "l"(p));
        }

        float acc[2][8][4];
#pragma unroll
        for (int mt = 0; mt < 2; mt++)
#pragma unroll
            for (int t = 0; t < 8; t++)
#pragma unroll
                for (int q = 0; q < 4; q++) acc[mt][t][q] = 0.0f;

        if (step > 0) {
            const __half* habase = g_ha[(step - 1) & 1] + dir * Bq * Hq;
            // B0,B1,B2 already in flight (prefetched before the group barrier).
            load_A(0, 0, habase);
            load_A(1, 64, habase);

            for (int kc = 0; kc < 8; kc++) {       // BK = 64 halves, stages kc%3
                if (kc < 7) asm volatile("cp.async.wait_group 1;");
                else        asm volatile("cp.async.wait_group 0;");
                __syncthreads();
                if (kc == 0)      load_A(2, 128, habase);          // B2 resident
                else if (kc <= 5) load_AB((kc + 2) % 3, (kc + 2) * 64, habase);

                uint32_t sa = (uint32_t)((kc % 3) * R_ASZ * 4);
                uint32_t sb = (uint32_t)((kc % 3) * R_BSZ * 4);
#pragma unroll
                for (int g = 0; g < 4; g++) {
                    uint32_t kby = g * 32;
                    uint32_t af[2][4], bf[8][2];
#pragma unroll
                    for (int mt = 0; mt < 2; mt++)
                        LDSM_X4(af[mt][0], af[mt][1], af[mt][2], af[mt][3],
                                aAddr + sa + (uint32_t)(mt * 16 * 36 * 4) + kby);
#pragma unroll
                    for (int p = 0; p < 4; p++)
                        LDSM_X4(bf[2 * p][0], bf[2 * p + 1][0], bf[2 * p][1], bf[2 * p + 1][1],
                                bAddr + sb + (uint32_t)(p * 64 * 36 * 4) + kby);
#pragma unroll
                    for (int mt = 0; mt < 2; mt++)
#pragma unroll
                        for (int t = 0; t < 8; t++) {
                            asm volatile(
                                "mma.sync.aligned.m16n8k16.row.col.f32.f16.f16.f32 "
                                "{%0,%1,%2,%3}, {%4,%5,%6,%7}, {%8,%9}, {%0,%1,%2,%3};"
                                : "+f"(acc[mt][t][0]), "+f"(acc[mt][t][1]),
                                  "+f"(acc[mt][t][2]), "+f"(acc[mt][t][3])
                                : "r"(af[mt][0]), "r"(af[mt][1]), "r"(af[mt][2]), "r"(af[mt][3]),
                                  "r"(bf[t][0]), "r"(bf[t][1]));
                        }
                }
            }
        }

        // all stages consumed; prefetch next step's weight chunks across the barrier
        __syncthreads();
        if (step < Wq - 1) {
            load_B(0, 0);
            load_B(1, 64);
            load_B(2, 128);
        }

        // ---- stage gates into dedicated smem ----
#pragma unroll
        for (int mt = 0; mt < 2; mt++)
#pragma unroll
            for (int t = 0; t < 8; t++)
#pragma unroll
                for (int rs = 0; rs < 2; rs++) {
                    int mr = wm * 32 + mt * 16 + gid + rs * 8;
                    int nc = ((t >> 1) << 6) + wn * 16 + ((t & 1) << 3) + tg * 2;
                    float2 v;
                    v.x = acc[mt][t][rs * 2];
                    v.y = acc[mt][t][rs * 2 + 1];
                    *(float2*)&gsm[mr * GSM_STRIDE + nc] = v;
                }
        __syncthreads();

        // ---- coalesced fused gate epilogue (xg read as half2) ----
        __half* haw = g_ha[step & 1] + dir * Bq * Hq;
        int hl = (tid & 31) * 2;
        int mb = tid >> 5;
#pragma unroll
        for (int mm = 0; mm < 8; mm++) {
            int m = mb + mm * 8;
            int gm = m0 + m;
            const float* gr = &gsm[m * GSM_STRIDE];
            const __half* xp = xgd + ((size_t)gm * Wq + t_) * G4 + ht0 + hl;
            float2 gi = *(const float2*)&gr[hl];
            float2 gf = *(const float2*)&gr[64 + hl];
            float2 gg = *(const float2*)&gr[128 + hl];
            float2 go = *(const float2*)&gr[192 + hl];
            float2 xi  = __half22float2(*(const __half2*)&xp[0]);
            float2 xf  = __half22float2(*(const __half2*)&xp[512]);
            float2 xgg = __half22float2(*(const __half2*)&xp[1024]);
            float2 xo  = __half22float2(*(const __half2*)&xp[1536]);
            int ci = dir * Bq * Hq + gm * Hq + ht0 + hl;
            float2 cprev = (step == 0) ? make_float2(0.f, 0.f) : *(const float2*)&g_c[ci];
            float2 cv, hv;
            cv.x = sig_fast(gf.x + xf.x) * cprev.x + sig_fast(gi.x + xi.x) * tanh_fast(gg.x + xgg.x);
            cv.y = sig_fast(gf.y + xf.y) * cprev.y + sig_fast(gi.y + xi.y) * tanh_fast(gg.y + xgg.y);
            hv.x = sig_fast(go.x + xo.x) * tanh_fast(cv.x);
            hv.y = sig_fast(go.y + xo.y) * tanh_fast(cv.y);
            *(float2*)&g_c[ci] = cv;
            __half2 hh = __floats2half2_rn(hv.x, hv.y);
            *(__half2*)&haw[gm * Hq + ht0 + hl] = hh;
            size_t so = ((size_t)gm * Wq + t_) * (2 * Hq) + dir * Hq + ht0 + hl;
            if (LAYER0) {
                *(__half2*)&g_hseq_h[so] = hh;
            } else {
                *(float2*)&g_hseq[so] = hv;
            }
        }

        // ---- group-local barrier (8 CTAs sharing (dir, m0)) ----
        if (step < Wq - 1) {
            __threadfence();
            __syncthreads();
            if (tid == 0) {
                unsigned* ctr = &g_gbar[bar_ofs + grp * Wq + step];
                atomicAdd(ctr, 1u);
                unsigned v;
                do {
                    asm volatile("ld.acquire.gpu.u32 %0, [%1];"
                                 : "=r"(v) : "l"(ctr) : "memory");
                    if (v < 8u) __nanosleep(32);
                } while (v < 8u);
            }
            __syncthreads();
        }
    }
}

// ---------------- final gather at t = len-1 ----------------
__global__ void gather_kernel(const int* __restrict__ qlen, float* __restrict__ out) {
    int idx = blockIdx.x * blockDim.x + threadIdx.x;
    if (idx >= Bq * 2 * Hq) return;
    int b = idx / (2 * Hq);
    int j = idx - b * (2 * Hq);
    int t = qlen[b] - 1;
    out[idx] = g_hseq[((size_t)b * Wq + t) * (2 * Hq) + j];
}

// ---------------- launch ----------------
extern "C" void kernel_launch(void* const* d_in, const int* in_sizes, int n_in,
                              void* d_out, int out_size)
{
    const int*   ques = (const int*)d_in[0];
    const int*   qlen = (const int*)d_in[1];
    const float* lut  = (const float*)d_in[2];
    const float* wih0 = (const float*)d_in[3];
    const float* whh0 = (const float*)d_in[4];
    const float* b0   = (const float*)d_in[5];
    const float* wih1 = (const float*)d_in[6];
    const float* whh1 = (const float*)d_in[7];
    const float* b1   = (const float*)d_in[8];
    float* out = (float*)d_out;

    __half *emb, *hseq_h, *wr, *xg;
    cudaGetSymbolAddress((void**)&emb,    g_emb);
    cudaGetSymbolAddress((void**)&xg,     g_xg);
    cudaGetSymbolAddress((void**)&hseq_h, g_hseq_h);
    cudaGetSymbolAddress((void**)&wr,     g_wr);

    cudaFuncSetAttribute(gemm_hf<1>, cudaFuncAttributeMaxDynamicSharedMemorySize, P_SMEM);
    cudaFuncSetAttribute(lstm_persist<0>, cudaFuncAttributeMaxDynamicSharedMemorySize, R_SMEM);
    cudaFuncSetAttribute(lstm_persist<1>, cudaFuncAttributeMaxDynamicSharedMemorySize, R_SMEM);

    // 0) fused: all weights -> half + barrier zeroing; table build
    cvt_all_weights_kernel<<<(W_TOTAL / 4 + 255) / 256, 256>>>(wih0, whh0, wih1, whh1);
    {
        dim3 grid((Vq + 31) / 32, Eq / 32);
        tanh_transpose_kernel<<<grid, dim3(32, 8)>>>(lut);
    }

    // 1) embedding
    embed_kernel<<<(Bq * Wq * Eq / 2 + 255) / 256, 256>>>(ques);

    // 2) layer-0 input projection (fp16 mma, half output)
    {
        dim3 grid(G4 / 128, (Bq * Wq) / 128, 2);
        gemm_hf<1><<<grid, 256, P_SMEM>>>(emb, 0,
                                          wr + OFF_WIH0, (size_t)G4 * Eq,
                                          b0,
                                          xg, (size_t)Bq * Wq * G4,
                                          Bq * Wq, G4, Eq);
    }

    // 3) layer-0 recurrence (writes half hseq)
    lstm_persist<1><<<NCTA, 256, R_SMEM>>>(wr + OFF_WHH0, xg, 0);

    // 4) layer-1 input projection (K = 2H, A = half hseq)
    {
        dim3 grid(G4 / 128, (Bq * Wq) / 128, 2);
        gemm_hf<1><<<grid, 256, P_SMEM>>>(hseq_h, 0,
                                          wr + OFF_WIH1, (size_t)G4 * 2 * Hq,
                                          b1,
                                          xg, (size_t)Bq * Wq * G4,
                                          Bq * Wq, G4, 2 * Hq);
    }

    // 5) layer-1 recurrence (writes f32 hseq for gather)
    lstm_persist<0><<<NCTA, 256, R_SMEM>>>(wr + OFF_WHH1, xg, 16 * Wq);

    // 6) gather
    gather_kernel<<<(Bq * 2 * Hq + 255) / 256, 256>>>(qlen, out);
}

// round 14
// speedup vs baseline: 1.9851x; 1.1483x over previous
#include <cuda_runtime.h>
#include <cuda_fp16.h>
#include <math.h>
#include <stdint.h>

#define Bq 512
#define Wq 40
#define Vq 12000
#define Eq 512
#define Hq 512
#define G4 2048   // 4*H
#define R_NCTA 256

// ---------------- scratch (device globals; no allocation) ----------------
__device__ __half g_table[(size_t)Vq * Eq];       // half tanh(lut^T)
__device__ __half g_emb[Bq * Wq * Eq];            // half embeddings
__device__ __half g_xg[2 * (size_t)Bq * Wq * G4]; // per-dir input projections (half)
__device__ float g_hseq[Bq * Wq * 2 * Hq];        // layer-1 output (f32, for gather)
__device__ __half g_hseq_h[Bq * Wq * 2 * Hq];     // layer-0 output (half, feeds proj-1)
__device__ __half g_ha[2][2 * Bq * Hq];           // h ping-pong (half, GEMM A)
__device__ float g_c[2 * Bq * Hq];
__device__ __half g_wr[10485760];                 // half weights: wih0|whh0|wih1|whh1
__device__ unsigned g_gbar[2 * 32 * Wq];          // group barriers [layer][group][step]

#define OFF_WIH0 0
#define OFF_WHH0 2097152
#define OFF_WIH1 4194304
#define OFF_WHH1 8388608
#define W_TOTAL  10485760

__device__ __forceinline__ float sig_fast(float x) {
    return __fdividef(1.0f, 1.0f + __expf(-x));
}
__device__ __forceinline__ float tanh_fast(float x) {
    return 2.0f * __fdividef(1.0f, 1.0f + __expf(-2.0f * x)) - 1.0f;
}
__device__ __forceinline__ void cp16(uint32_t dst, const void* src) {
    asm volatile("cp.async.cg.shared.global [%0], [%1], 16;" :: "r"(dst), "l"(src));
}
#define LDSM_X4(r0, r1, r2, r3, addr) \
    asm volatile("ldmatrix.sync.aligned.m8n8.x4.shared.b16 {%0,%1,%2,%3}, [%4];" \
                 : "=r"(r0), "=r"(r1), "=r"(r2), "=r"(r3) : "r"(addr))

// ---------------- one-time: all weights -> half, zero barriers (fused) ----------
__global__ void cvt_all_weights_kernel(const float* __restrict__ w0, const float* __restrict__ w1,
                                       const float* __restrict__ w2, const float* __restrict__ w3) {
    int i = blockIdx.x * blockDim.x + threadIdx.x;     // one thread = 4 floats
    if (i < 2 * 32 * Wq) g_gbar[i] = 0;
    int idx4 = i * 4;
    if (idx4 >= W_TOTAL) return;
    const float* src; int off;
    if (idx4 < OFF_WHH0)      { src = w0; off = idx4; }
    else if (idx4 < OFF_WIH1) { src = w1; off = idx4 - OFF_WHH0; }
    else if (idx4 < OFF_WHH1) { src = w2; off = idx4 - OFF_WIH1; }
    else                      { src = w3; off = idx4 - OFF_WHH1; }
    float4 v = *(const float4*)(src + off);
    __half2 a = __floats2half2_rn(v.x, v.y);
    __half2 b = __floats2half2_rn(v.z, v.w);
    __half2* dst = (__half2*)&g_wr[idx4];
    dst[0] = a; dst[1] = b;
}

// ---------------- tanh + transpose lookup: g_table[v][e] = h(tanh(lut[e][v])) ----
__global__ void tanh_transpose_kernel(const float* __restrict__ lut) {
    __shared__ float tile[32][33];
    int v0 = blockIdx.x * 32;
    int e0 = blockIdx.y * 32;
    int tx = threadIdx.x, ty = threadIdx.y;
#pragma unroll
    for (int i = ty; i < 32; i += 8) {
        int e = e0 + i, v = v0 + tx;
        tile[i][tx] = (v < Vq) ? lut[(size_t)e * Vq + v] : 0.0f;
    }
    __syncthreads();
#pragma unroll
    for (int i = ty; i < 32; i += 8) {
        int v = v0 + i, e = e0 + tx;
        if (v < Vq) g_table[(size_t)v * Eq + e] = __float2half_rn(tanhf(tile[tx][i]));
    }
}

// ---------------- embedding gather (u32 granularity = 2 halves) ----------------
__global__ void embed_kernel(const int* __restrict__ ques) {
    int idx = blockIdx.x * blockDim.x + threadIdx.x;   // over u32s
    if (idx >= Bq * Wq * Eq / 2) return;
    int e2 = idx & 255;
    int bw = idx >> 8;
    int v = ques[bw];
    uint32_t val = 0;
    if (v > 0) val = ((const uint32_t*)g_table)[(size_t)(v - 1) * 256 + e2];
    ((uint32_t*)g_emb)[idx] = val;
}

// ---------------- FP16 tensor-core NT GEMM, 4-stage cp.async + ldmatrix --------
// (unchanged from R13 — measured at ~97% of the mma.sync issue ceiling)
#define P_ASZ (128 * 20)            // u32 per stage
#define P_SMEM (4 * P_ASZ * 2 * 4)  // 81920 B
template <int HAS_BIAS>
__global__ __launch_bounds__(256, 2) void gemm_hf(
    const __half* __restrict__ A, size_t aDirStride,
    const __half* __restrict__ Bw, size_t bDirStride,
    const float* __restrict__ bias,
    __half* __restrict__ C, size_t cDirStride,
    int M, int N, int K)
{
    extern __shared__ uint32_t sm[];
    uint32_t* smA = sm;                 // [4][128][20]
    uint32_t* smB = sm + 4 * P_ASZ;
    uint32_t baseA = (uint32_t)__cvta_generic_to_shared(smA);
    uint32_t baseB = (uint32_t)__cvta_generic_to_shared(smB);

    int dir = blockIdx.z;
    A  += (size_t)dir * aDirStride;
    Bw += (size_t)dir * bDirStride;
    C  += (size_t)dir * cDirStride;

    int m0 = blockIdx.y * 128;
    int n0 = blockIdx.x * 128;
    int tid = threadIdx.x;
    int wid = tid >> 5, lane = tid & 31;
    int wm = wid >> 2, wn = wid & 3;
    int gid = lane >> 2, tg = lane & 3;

    int lrow = (lane & 7) + ((lane >> 3) & 1) * 8;
    int lk = (lane >> 4) * 4;
    uint32_t aAddr = baseA + (uint32_t)(((wm * 64 + lrow) * 20 + lk) * 4);
    uint32_t bAddr = baseB + (uint32_t)(((wn * 32 + lrow) * 20 + lk) * 4);

    float acc[4][4][4];
#pragma unroll
    for (int mt = 0; mt < 4; mt++)
#pragma unroll
        for (int nt = 0; nt < 4; nt++)
#pragma unroll
            for (int r = 0; r < 4; r++) acc[mt][nt][r] = 0.0f;

    int niter = K >> 5;                 // BK = 32 halves

    auto load_stage = [&](int s, int k0) {
#pragma unroll
        for (int i = 0; i < 2; i++) {
            int c = tid + i * 256;
            int row = c >> 2, seg = c & 3;
            cp16(baseA + (s * P_ASZ + row * 20 + seg * 4) * 4,
                 A + (size_t)(m0 + row) * K + k0 + seg * 8);
            cp16(baseB + (s * P_ASZ + row * 20 + seg * 4) * 4,
                 Bw + (size_t)(n0 + row) * K + k0 + seg * 8);
        }
        asm volatile("cp.async.commit_group;");
    };

    load_stage(0, 0);
    load_stage(1, 32);
    load_stage(2, 64);

    for (int it = 0; it < niter; it++) {
        int rem = niter - 1 - it;
        if (rem >= 2)      asm volatile("cp.async.wait_group 2;");
        else if (rem == 1) asm volatile("cp.async.wait_group 1;");
        else               asm volatile("cp.async.wait_group 0;");
        __syncthreads();
        if (it + 3 < niter) load_stage((it + 3) & 3, (it + 3) * 32);

        uint32_t sofs = (uint32_t)((it & 3) * P_ASZ * 4);
#pragma unroll
        for (int g = 0; g < 2; g++) {
            uint32_t kby = g * 32;
            uint32_t af[4][4], bf[4][2];
#pragma unroll
            for (int mt = 0; mt < 4; mt++)
                LDSM_X4(af[mt][0], af[mt][1], af[mt][2], af[mt][3],
                        aAddr + sofs + (uint32_t)(mt * 16 * 20 * 4) + kby);
#pragma unroll
            for (int p = 0; p < 2; p++)
                LDSM_X4(bf[2 * p][0], bf[2 * p + 1][0], bf[2 * p][1], bf[2 * p + 1][1],
                        bAddr + sofs + (uint32_t)(p * 16 * 20 * 4) + kby);
#pragma unroll
            for (int mt = 0; mt < 4; mt++)
#pragma unroll
                for (int nt = 0; nt < 4; nt++) {
                    asm volatile(
                        "mma.sync.aligned.m16n8k16.row.col.f32.f16.f16.f32 "
                        "{%0,%1,%2,%3}, {%4,%5,%6,%7}, {%8,%9}, {%0,%1,%2,%3};"
                        : "+f"(acc[mt][nt][0]), "+f"(acc[mt][nt][1]),
                          "+f"(acc[mt][nt][2]), "+f"(acc[mt][nt][3])
                        : "r"(af[mt][0]), "r"(af[mt][1]), "r"(af[mt][2]), "r"(af[mt][3]),
                          "r"(bf[nt][0]), "r"(bf[nt][1]));
                }
        }
    }

    const float* bp = bias + (size_t)dir * 2 * G4;
#pragma unroll
    for (int mt = 0; mt < 4; mt++) {
#pragma unroll
        for (int nt = 0; nt < 4; nt++) {
            int m = m0 + wm * 64 + mt * 16 + gid;
            int n = n0 + wn * 32 + nt * 8 + tg * 2;
            float2 v0, v1;
            v0.x = acc[mt][nt][0]; v0.y = acc[mt][nt][1];
            v1.x = acc[mt][nt][2]; v1.y = acc[mt][nt][3];
            if (HAS_BIAS) {
                float bx = bp[n] + bp[G4 + n];
                float by = bp[n + 1] + bp[G4 + n + 1];
                v0.x += bx; v0.y += by; v1.x += bx; v1.y += by;
            }
            *(__half2*)(C + (size_t)m * N + n) = __floats2half2_rn(v0.x, v0.y);
            *(__half2*)(C + (size_t)(m + 8) * N + n) = __floats2half2_rn(v1.x, v1.y);
        }
    }
}

// ---------------- persistent fused LSTM recurrence, 256 CTAs / 2 per SM --------
// CTA = (dir, 64 b-rows, 32 h-cols); gates tile 64x128; 8 warps of 32x32.
// 3-stage cp.async; smem layout B0|B1|A0|A1|A2|B2, gate staging ALIASED over
// A0..B2 (dead during staging; B0/B1 carry the cross-barrier weight prefetch).
// Group barrier: 16 CTAs sharing (dir, m0) = exact producers of this CTA's A.
#define R2_ASZ (64 * 36)        // u32
#define R2_BSZ (128 * 36)       // u32
#define R2_A0  (2 * R2_BSZ)                 // u32 offset of A stage 0
#define R2_B2  (2 * R2_BSZ + 3 * R2_ASZ)    // u32 offset of B stage 2
#define R2_SMEM ((3 * R2_BSZ + 3 * R2_ASZ) * 4)   // 82944 B
#define GSM_STRIDE 130
template <int LAYER0>
__global__ __launch_bounds__(256, 2) void lstm_persist(
    const __half* __restrict__ whh,      // [2 dirs][G4][Hq] half
    const __half* __restrict__ xg,       // [2 dirs][Bq][Wq][G4] half
    int bar_ofs)
{
    extern __shared__ uint32_t sm[];
    float* gsm = (float*)(sm + R2_A0);    // [64][130] aliases A0..B2
    uint32_t base = (uint32_t)__cvta_generic_to_shared(sm);

    int tid = threadIdx.x;
    int bx = blockIdx.x;
    int dir = bx >> 7;
    int r = bx & 127;
    int m0 = (r >> 4) * 64;
    int ht0 = (r & 15) * 32;
    int grp = bx >> 4;                    // 16-CTA group sharing (dir, m0)

    int wid = tid >> 5, lane = tid & 31;
    int wm = wid >> 2, wn = wid & 3;      // warp tile: 32 m x 32 n
    int gid = lane >> 2, tg = lane & 3;

    int lrow = (lane & 7) + ((lane >> 3) & 1) * 8;
    int lk = (lane >> 4) * 4;
    uint32_t aLane = base + (uint32_t)(((wm * 32 + lrow) * 36 + lk) * 4);
    uint32_t bLane = base + (uint32_t)(((wn * 32 + lrow) * 36 + lk) * 4);

    const __half* wbase = whh + (size_t)dir * G4 * Hq;
    const __half* xgd = xg + (size_t)dir * Bq * Wq * G4;

    auto aStage = [&](int s) -> uint32_t { return (uint32_t)((R2_A0 + s * R2_ASZ) * 4); };
    auto bStage = [&](int s) -> uint32_t {
        return (uint32_t)((s == 2 ? R2_B2 : s * R2_BSZ) * 4);
    };

    auto load_A = [&](int s, int k0, const __half* habase) {
        uint32_t ab = base + aStage(s);
#pragma unroll
        for (int i = 0; i < 2; i++) {
            int c = tid + i * 256;            // 64 rows x 8 segs
            int row = c >> 3, seg = c & 7;
            cp16(ab + (uint32_t)((row * 36 + seg * 4) * 4),
                 habase + (size_t)(m0 + row) * Hq + k0 + seg * 8);
        }
        asm volatile("cp.async.commit_group;");
    };
    auto load_Bw = [&](int s, int k0) {
        uint32_t bb = base + bStage(s);
#pragma unroll
        for (int i = 0; i < 4; i++) {
            int c = tid + i * 256;            // 128 rows x 8 segs
            int row = c >> 3, seg = c & 7;
            int grow = ((row >> 5) << 9) + ht0 + (row & 31);   // gate*512 + h
            cp16(bb + (uint32_t)((row * 36 + seg * 4) * 4),
                 wbase + (size_t)grow * Hq + k0 + seg * 8);
        }
        asm volatile("cp.async.commit_group;");
    };
    auto load_AB = [&](int s, int k0, const __half* habase) {
        uint32_t ab = base + aStage(s);
        uint32_t bb = base + bStage(s);
#pragma unroll
        for (int i = 0; i < 2; i++) {
            int c = tid + i * 256;
            int row = c >> 3, seg = c & 7;
            cp16(ab + (uint32_t)((row * 36 + seg * 4) * 4),
                 habase + (size_t)(m0 + row) * Hq + k0 + seg * 8);
        }
#pragma unroll
        for (int i = 0; i < 4; i++) {
            int c = tid + i * 256;
            int row = c >> 3, seg = c & 7;
            int grow = ((row >> 5) << 9) + ht0 + (row & 31);
            cp16(bb + (uint32_t)((row * 36 + seg * 4) * 4),
                 wbase + (size_t)grow * Hq + k0 + seg * 8);
        }
        asm volatile("cp.async.commit_group;");
    };

    for (int step = 0; step < Wq; step++) {
        int t_ = dir ? (Wq - 1 - step) : step;

        // L2-prefetch this step's xg slice (64 rows x 4 gate segs)
        if (tid < 256) {
            int row = tid >> 2, seg = tid & 3;
            const __half* p = xgd + ((size_t)(m0 + row) * Wq + t_) * G4
                              + seg * 512 + ht0;
            asm volatile("prefetch.global.L2 [%0];" :: "l"(p));
        }

        float acc[2][4][4];
#pragma unroll
        for (int mt = 0; mt < 2; mt++)
#pragma unroll
            for (int nt = 0; nt < 4; nt++)
#pragma unroll
                for (int q = 0; q < 4; q++) acc[mt][nt][q] = 0.0f;

        if (step > 0) {
            const __half* habase = g_ha[(step - 1) & 1] + dir * Bq * Hq;
            // B0,B1 already in flight (prefetched before the group barrier).
            load_A(0, 0, habase);
            load_A(1, 64, habase);

            for (int kc = 0; kc < 8; kc++) {       // BK = 64 halves, stage kc%3
                if (kc < 7) asm volatile("cp.async.wait_group 1;");
                else        asm volatile("cp.async.wait_group 0;");
                __syncthreads();
                if (kc == 0)      load_AB(2, 128, habase);
                else if (kc <= 5) load_AB((kc + 2) % 3, (kc + 2) * 64, habase);

                uint32_t sa = aStage(kc % 3);
                uint32_t sb = bStage(kc % 3);
#pragma unroll
                for (int g = 0; g < 4; g++) {
                    uint32_t kby = g * 32;
                    uint32_t af[2][4], bf[4][2];
#pragma unroll
                    for (int mt = 0; mt < 2; mt++)
                        LDSM_X4(af[mt][0], af[mt][1], af[mt][2], af[mt][3],
                                aLane + sa + (uint32_t)(mt * 16 * 36 * 4) + kby);
#pragma unroll
                    for (int p = 0; p < 2; p++)
                        LDSM_X4(bf[2 * p][0], bf[2 * p + 1][0], bf[2 * p][1], bf[2 * p + 1][1],
                                bLane + sb + (uint32_t)(p * 16 * 36 * 4) + kby);
#pragma unroll
                    for (int mt = 0; mt < 2; mt++)
#pragma unroll
                        for (int nt = 0; nt < 4; nt++) {
                            asm volatile(
                                "mma.sync.aligned.m16n8k16.row.col.f32.f16.f16.f32 "
                                "{%0,%1,%2,%3}, {%4,%5,%6,%7}, {%8,%9}, {%0,%1,%2,%3};"
                                : "+f"(acc[mt][nt][0]), "+f"(acc[mt][nt][1]),
                                  "+f"(acc[mt][nt][2]), "+f"(acc[mt][nt][3])
                                : "r"(af[mt][0]), "r"(af[mt][1]), "r"(af[mt][2]), "r"(af[mt][3]),
                                  "r"(bf[nt][0]), "r"(bf[nt][1]));
                        }
                }
            }
        }

        // all smem reads done; prefetch next step's weights into B0/B1 (disjoint
        // from the gsm alias region)
        __syncthreads();
        if (step < Wq - 1) {
            load_Bw(0, 0);
            load_Bw(1, 64);
        }

        // ---- stage gates into gsm (aliases A0..B2) ----
#pragma unroll
        for (int mt = 0; mt < 2; mt++)
#pragma unroll
            for (int nt = 0; nt < 4; nt++)
#pragma unroll
                for (int rs = 0; rs < 2; rs++) {
                    int mr = wm * 32 + mt * 16 + gid + rs * 8;
                    int nc = wn * 32 + nt * 8 + tg * 2;       // col = gate*32 + h
                    float2 v;
                    v.x = acc[mt][nt][rs * 2];
                    v.y = acc[mt][nt][rs * 2 + 1];
                    *(float2*)&gsm[mr * GSM_STRIDE + nc] = v;
                }
        __syncthreads();

        // ---- coalesced fused gate epilogue ----
        __half* haw = g_ha[step & 1] + dir * Bq * Hq;
        int hl = (tid & 15) * 2;
        int rb = tid >> 4;                 // 0..15
#pragma unroll
        for (int it = 0; it < 4; it++) {
            int m = it * 16 + rb;          // local row 0..63
            int gm = m0 + m;
            const float* gr = &gsm[m * GSM_STRIDE];
            const __half* xp = xgd + ((size_t)gm * Wq + t_) * G4 + ht0 + hl;
            float2 gi = *(const float2*)&gr[hl];
            float2 gf = *(const float2*)&gr[32 + hl];
            float2 gg = *(const float2*)&gr[64 + hl];
            float2 go = *(const float2*)&gr[96 + hl];
            float2 xi  = __half22float2(*(const __half2*)&xp[0]);
            float2 xf  = __half22float2(*(const __half2*)&xp[512]);
            float2 xgg = __half22float2(*(const __half2*)&xp[1024]);
            float2 xo  = __half22float2(*(const __half2*)&xp[1536]);
            int ci = dir * Bq * Hq + gm * Hq + ht0 + hl;
            float2 cprev = (step == 0) ? make_float2(0.f, 0.f) : *(const float2*)&g_c[ci];
            float2 cv, hv;
            cv.x = sig_fast(gf.x + xf.x) * cprev.x + sig_fast(gi.x + xi.x) * tanh_fast(gg.x + xgg.x);
            cv.y = sig_fast(gf.y + xf.y) * cprev.y + sig_fast(gi.y + xi.y) * tanh_fast(gg.y + xgg.y);
            hv.x = sig_fast(go.x + xo.x) * tanh_fast(cv.x);
            hv.y = sig_fast(go.y + xo.y) * tanh_fast(cv.y);
            *(float2*)&g_c[ci] = cv;
            __half2 hh = __floats2half2_rn(hv.x, hv.y);
            *(__half2*)&haw[gm * Hq + ht0 + hl] = hh;
            size_t so = ((size_t)gm * Wq + t_) * (2 * Hq) + dir * Hq + ht0 + hl;
            if (LAYER0) {
                *(__half2*)&g_hseq_h[so] = hh;
            } else {
                *(float2*)&g_hseq[so] = hv;
            }
        }

        // ---- group-local barrier (16 CTAs sharing (dir, m0)) ----
        if (step < Wq - 1) {
            __threadfence();
            __syncthreads();
            if (tid == 0) {
                unsigned* ctr = &g_gbar[bar_ofs + grp * Wq + step];
                atomicAdd(ctr, 1u);
                unsigned v;
                do {
                    asm volatile("ld.acquire.gpu.u32 %0, [%1];"
                                 : "=r"(v) : "l"(ctr) : "memory");
                    if (v < 16u) __nanosleep(32);
                } while (v < 16u);
            }
            __syncthreads();
        }
    }
}

// ---------------- final gather at t = len-1 ----------------
__global__ void gather_kernel(const int* __restrict__ qlen, float* __restrict__ out) {
    int idx = blockIdx.x * blockDim.x + threadIdx.x;
    if (idx >= Bq * 2 * Hq) return;
    int b = idx / (2 * Hq);
    int j = idx - b * (2 * Hq);
    int t = qlen[b] - 1;
    out[idx] = g_hseq[((size_t)b * Wq + t) * (2 * Hq) + j];
}

// ---------------- launch ----------------
extern "C" void kernel_launch(void* const* d_in, const int* in_sizes, int n_in,
                              void* d_out, int out_size)
{
    const int*   ques = (const int*)d_in[0];
    const int*   qlen = (const int*)d_in[1];
    const float* lut  = (const float*)d_in[2];
    const float* wih0 = (const float*)d_in[3];
    const float* whh0 = (const float*)d_in[4];
    const float* b0   = (const float*)d_in[5];
    const float* wih1 = (const float*)d_in[6];
    const float* whh1 = (const float*)d_in[7];
    const float* b1   = (const float*)d_in[8];
    float* out = (float*)d_out;

    __half *emb, *hseq_h, *wr, *xg;
    cudaGetSymbolAddress((void**)&emb,    g_emb);
    cudaGetSymbolAddress((void**)&xg,     g_xg);
    cudaGetSymbolAddress((void**)&hseq_h, g_hseq_h);
    cudaGetSymbolAddress((void**)&wr,     g_wr);

    cudaFuncSetAttribute(gemm_hf<1>, cudaFuncAttributeMaxDynamicSharedMemorySize, P_SMEM);
    cudaFuncSetAttribute(lstm_persist<0>, cudaFuncAttributeMaxDynamicSharedMemorySize, R2_SMEM);
    cudaFuncSetAttribute(lstm_persist<1>, cudaFuncAttributeMaxDynamicSharedMemorySize, R2_SMEM);

    // 0) fused: all weights -> half + barrier zeroing; table build
    cvt_all_weights_kernel<<<(W_TOTAL / 4 + 255) / 256, 256>>>(wih0, whh0, wih1, whh1);
    {
        dim3 grid((Vq + 31) / 32, Eq / 32);
        tanh_transpose_kernel<<<grid, dim3(32, 8)>>>(lut);
    }

    // 1) embedding
    embed_kernel<<<(Bq * Wq * Eq / 2 + 255) / 256, 256>>>(ques);

    // 2) layer-0 input projection (fp16 mma, half output)
    {
        dim3 grid(G4 / 128, (Bq * Wq) / 128, 2);
        gemm_hf<1><<<grid, 256, P_SMEM>>>(emb, 0,
                                          wr + OFF_WIH0, (size_t)G4 * Eq,
                                          b0,
                                          xg, (size_t)Bq * Wq * G4,
                                          Bq * Wq, G4, Eq);
    }

    // 3) layer-0 recurrence (writes half hseq)
    lstm_persist<1><<<R_NCTA, 256, R2_SMEM>>>(wr + OFF_WHH0, xg, 0);

    // 4) layer-1 input projection (K = 2H, A = half hseq)
    {
        dim3 grid(G4 / 128, (Bq * Wq) / 128, 2);
        gemm_hf<1><<<grid, 256, P_SMEM>>>(hseq_h, 0,
                                          wr + OFF_WIH1, (size_t)G4 * 2 * Hq,
                                          b1,
                                          xg, (size_t)Bq * Wq * G4,
                                          Bq * Wq, G4, 2 * Hq);
    }

    // 5) layer-1 recurrence (writes f32 hseq for gather)
    lstm_persist<0><<<R_NCTA, 256, R2_SMEM>>>(wr + OFF_WHH1, xg, 32 * Wq);

    // 6) gather
    gather_kernel<<<(Bq * 2 * Hq + 255) / 256, 256>>>(qlen, out);
}

// round 15
// speedup vs baseline: 2.0160x; 1.0155x over previous
#include <cuda_runtime.h>
#include <cuda_fp16.h>
#include <math.h>
#include <stdint.h>

#define Bq 512
#define Wq 40
#define Vq 12000
#define Eq 512
#define Hq 512
#define G4 2048   // 4*H
#define R_NCTA 256

// ---------------- scratch (device globals; no allocation) ----------------
__device__ __half g_table[(size_t)Vq * Eq];       // half tanh(lut^T)
__device__ __half g_xg[2 * (size_t)Bq * Wq * G4]; // per-dir input projections (half)
__device__ __half g_hseq_h[Bq * Wq * 2 * Hq];     // layer-0 output (half; also next-A)
__device__ __half g_ha[2][2 * Bq * Hq];           // h ping-pong (layer-1 A)
__device__ float g_c[2 * Bq * Hq];
__device__ __half g_wr[10485760];                 // half weights: wih0|whh0|wih1|whh1
__device__ unsigned g_gbar[2 * 32 * Wq];          // group barriers [layer][group][step]

#define OFF_WIH0 0
#define OFF_WHH0 2097152
#define OFF_WIH1 4194304
#define OFF_WHH1 8388608
#define W_TOTAL  10485760

__device__ __forceinline__ float sig_fast(float x) {
    return __fdividef(1.0f, 1.0f + __expf(-x));
}
__device__ __forceinline__ float tanh_fast(float x) {
    return 2.0f * __fdividef(1.0f, 1.0f + __expf(-2.0f * x)) - 1.0f;
}
__device__ __forceinline__ void cp16(uint32_t dst, const void* src) {
    asm volatile("cp.async.cg.shared.global [%0], [%1], 16;" :: "r"(dst), "l"(src));
}
// cp.async with src_size: bytes beyond src_size are zero-filled
__device__ __forceinline__ void cp16z(uint32_t dst, const void* src, int sz) {
    asm volatile("cp.async.cg.shared.global [%0], [%1], 16, %2;"
                 :: "r"(dst), "l"(src), "r"(sz));
}
#define LDSM_X4(r0, r1, r2, r3, addr) \
    asm volatile("ldmatrix.sync.aligned.m8n8.x4.shared.b16 {%0,%1,%2,%3}, [%4];" \
                 : "=r"(r0), "=r"(r1), "=r"(r2), "=r"(r3) : "r"(addr))

// ---------------- one-time: all weights -> half, zero barriers (fused) ----------
__global__ void cvt_all_weights_kernel(const float* __restrict__ w0, const float* __restrict__ w1,
                                       const float* __restrict__ w2, const float* __restrict__ w3) {
    int i = blockIdx.x * blockDim.x + threadIdx.x;     // one thread = 4 floats
    if (i < 2 * 32 * Wq) g_gbar[i] = 0;
    int idx4 = i * 4;
    if (idx4 >= W_TOTAL) return;
    const float* src; int off;
    if (idx4 < OFF_WHH0)      { src = w0; off = idx4; }
    else if (idx4 < OFF_WIH1) { src = w1; off = idx4 - OFF_WHH0; }
    else if (idx4 < OFF_WHH1) { src = w2; off = idx4 - OFF_WIH1; }
    else                      { src = w3; off = idx4 - OFF_WHH1; }
    float4 v = *(const float4*)(src + off);
    __half2 a = __floats2half2_rn(v.x, v.y);
    __half2 b = __floats2half2_rn(v.z, v.w);
    __half2* dst = (__half2*)&g_wr[idx4];
    dst[0] = a; dst[1] = b;
}

// ---------------- tanh + transpose lookup: g_table[v][e] = h(tanh(lut[e][v])) ----
__global__ void tanh_transpose_kernel(const float* __restrict__ lut) {
    __shared__ float tile[32][33];
    int v0 = blockIdx.x * 32;
    int e0 = blockIdx.y * 32;
    int tx = threadIdx.x, ty = threadIdx.y;
#pragma unroll
    for (int i = ty; i < 32; i += 8) {
        int e = e0 + i, v = v0 + tx;
        tile[i][tx] = (v < Vq) ? lut[(size_t)e * Vq + v] : 0.0f;
    }
    __syncthreads();
#pragma unroll
    for (int i = ty; i < 32; i += 8) {
        int v = v0 + i, e = e0 + tx;
        if (v < Vq) g_table[(size_t)v * Eq + e] = __float2half_rn(tanhf(tile[tx][i]));
    }
}

// ---------------- FP16 tensor-core NT GEMM, 4-stage cp.async + ldmatrix --------
// EMB=1: A rows gathered from g_table via ques (v==0 -> zero row).
#define P_ASZ (128 * 20)            // u32 per stage
#define P_SMEM (4 * P_ASZ * 2 * 4)  // 81920 B
template <int HAS_BIAS, int EMB>
__global__ __launch_bounds__(256, 2) void gemm_hf(
    const __half* __restrict__ A, size_t aDirStride,
    const __half* __restrict__ Bw, size_t bDirStride,
    const float* __restrict__ bias,
    __half* __restrict__ C, size_t cDirStride,
    int M, int N, int K,
    const int* __restrict__ ques)
{
    extern __shared__ uint32_t sm[];
    uint32_t* smA = sm;                 // [4][128][20]
    uint32_t* smB = sm + 4 * P_ASZ;
    uint32_t baseA = (uint32_t)__cvta_generic_to_shared(smA);
    uint32_t baseB = (uint32_t)__cvta_generic_to_shared(smB);

    int dir = blockIdx.z;
    A  += (size_t)dir * aDirStride;
    Bw += (size_t)dir * bDirStride;
    C  += (size_t)dir * cDirStride;

    int m0 = blockIdx.y * 128;
    int n0 = blockIdx.x * 128;
    int tid = threadIdx.x;
    int wid = tid >> 5, lane = tid & 31;
    int wm = wid >> 2, wn = wid & 3;
    int gid = lane >> 2, tg = lane & 3;

    // gathered-A row indices are loop-invariant per thread
    int r0 = tid >> 2;                 // i=0 row
    int seg0 = tid & 3;
    long arow0 = 0, arow1 = 0;
    int asz0 = 16, asz1 = 16;
    if (EMB) {
        int v0 = ques[m0 + r0];
        int v1 = ques[m0 + r0 + 64];
        arow0 = (long)(v0 > 0 ? v0 - 1 : 0) * Eq;
        arow1 = (long)(v1 > 0 ? v1 - 1 : 0) * Eq;
        asz0 = v0 > 0 ? 16 : 0;
        asz1 = v1 > 0 ? 16 : 0;
    }

    int lrow = (lane & 7) + ((lane >> 3) & 1) * 8;
    int lk = (lane >> 4) * 4;
    uint32_t aAddr = baseA + (uint32_t)(((wm * 64 + lrow) * 20 + lk) * 4);
    uint32_t bAddr = baseB + (uint32_t)(((wn * 32 + lrow) * 20 + lk) * 4);

    float acc[4][4][4];
#pragma unroll
    for (int mt = 0; mt < 4; mt++)
#pragma unroll
        for (int nt = 0; nt < 4; nt++)
#pragma unroll
            for (int r = 0; r < 4; r++) acc[mt][nt][r] = 0.0f;

    int niter = K >> 5;                 // BK = 32 halves

    auto load_stage = [&](int s, int k0) {
#pragma unroll
        for (int i = 0; i < 2; i++) {
            int c = tid + i * 256;
            int row = c >> 2, seg = c & 3;
            uint32_t da = baseA + (s * P_ASZ + row * 20 + seg * 4) * 4;
            if (EMB) {
                cp16z(da, A + (i ? arow1 : arow0) + k0 + seg0 * 8, i ? asz1 : asz0);
            } else {
                cp16(da, A + (size_t)(m0 + row) * K + k0 + seg * 8);
            }
            cp16(baseB + (s * P_ASZ + row * 20 + seg * 4) * 4,
                 Bw + (size_t)(n0 + row) * K + k0 + seg * 8);
        }
        asm volatile("cp.async.commit_group;");
    };

    load_stage(0, 0);
    load_stage(1, 32);
    load_stage(2, 64);

    for (int it = 0; it < niter; it++) {
        int rem = niter - 1 - it;
        if (rem >= 2)      asm volatile("cp.async.wait_group 2;");
        else if (rem == 1) asm volatile("cp.async.wait_group 1;");
        else               asm volatile("cp.async.wait_group 0;");
        __syncthreads();
        if (it + 3 < niter) load_stage((it + 3) & 3, (it + 3) * 32);

        uint32_t sofs = (uint32_t)((it & 3) * P_ASZ * 4);
#pragma unroll
        for (int g = 0; g < 2; g++) {
            uint32_t kby = g * 32;
            uint32_t af[4][4], bf[4][2];
#pragma unroll
            for (int mt = 0; mt < 4; mt++)
                LDSM_X4(af[mt][0], af[mt][1], af[mt][2], af[mt][3],
                        aAddr + sofs + (uint32_t)(mt * 16 * 20 * 4) + kby);
#pragma unroll
            for (int p = 0; p < 2; p++)
                LDSM_X4(bf[2 * p][0], bf[2 * p + 1][0], bf[2 * p][1], bf[2 * p + 1][1],
                        bAddr + sofs + (uint32_t)(p * 16 * 20 * 4) + kby);
#pragma unroll
            for (int mt = 0; mt < 4; mt++)
#pragma unroll
                for (int nt = 0; nt < 4; nt++) {
                    asm volatile(
                        "mma.sync.aligned.m16n8k16.row.col.f32.f16.f16.f32 "
                        "{%0,%1,%2,%3}, {%4,%5,%6,%7}, {%8,%9}, {%0,%1,%2,%3};"
                        : "+f"(acc[mt][nt][0]), "+f"(acc[mt][nt][1]),
                          "+f"(acc[mt][nt][2]), "+f"(acc[mt][nt][3])
                        : "r"(af[mt][0]), "r"(af[mt][1]), "r"(af[mt][2]), "r"(af[mt][3]),
                          "r"(bf[nt][0]), "r"(bf[nt][1]));
                }
        }
    }

    const float* bp = bias + (size_t)dir * 2 * G4;
#pragma unroll
    for (int mt = 0; mt < 4; mt++) {
#pragma unroll
        for (int nt = 0; nt < 4; nt++) {
            int m = m0 + wm * 64 + mt * 16 + gid;
            int n = n0 + wn * 32 + nt * 8 + tg * 2;
            float2 v0, v1;
            v0.x = acc[mt][nt][0]; v0.y = acc[mt][nt][1];
            v1.x = acc[mt][nt][2]; v1.y = acc[mt][nt][3];
            if (HAS_BIAS) {
                float bx = bp[n] + bp[G4 + n];
                float by = bp[n + 1] + bp[G4 + n + 1];
                v0.x += bx; v0.y += by; v1.x += bx; v1.y += by;
            }
            *(__half2*)(C + (size_t)m * N + n) = __floats2half2_rn(v0.x, v0.y);
            *(__half2*)(C + (size_t)(m + 8) * N + n) = __floats2half2_rn(v1.x, v1.y);
        }
    }
}

// ---------------- persistent fused LSTM recurrence, 256 CTAs / 2 per SM --------
// LAYER0=1: A read from g_hseq_h[b][t_prev] (no g_ha write); h written to hseq_h.
// LAYER0=0: A read from g_ha ping-pong; h written to g_ha; final h written
//           directly to out when t_ == qlen[b]-1 (gather fused away).
#define R2_ASZ (64 * 36)        // u32
#define R2_BSZ (128 * 36)       // u32
#define R2_A0  (2 * R2_BSZ)                 // u32 offset of A stage 0
#define R2_B2  (2 * R2_BSZ + 3 * R2_ASZ)    // u32 offset of B stage 2
#define R2_SMEM ((3 * R2_BSZ + 3 * R2_ASZ) * 4)   // 82944 B
#define GSM_STRIDE 130
template <int LAYER0>
__global__ __launch_bounds__(256, 2) void lstm_persist(
    const __half* __restrict__ whh,      // [2 dirs][G4][Hq] half
    const __half* __restrict__ xg,       // [2 dirs][Bq][Wq][G4] half
    const int* __restrict__ qlen,
    float* __restrict__ out,
    int bar_ofs)
{
    extern __shared__ uint32_t sm[];
    float* gsm = (float*)(sm + R2_A0);    // [64][130] aliases A0..B2
    uint32_t base = (uint32_t)__cvta_generic_to_shared(sm);

    int tid = threadIdx.x;
    int bx = blockIdx.x;
    int dir = bx >> 7;
    int r = bx & 127;
    int m0 = (r >> 4) * 64;
    int ht0 = (r & 15) * 32;
    int grp = bx >> 4;                    // 16-CTA group sharing (dir, m0)

    int wid = tid >> 5, lane = tid & 31;
    int wm = wid >> 2, wn = wid & 3;      // warp tile: 32 m x 32 n
    int gid = lane >> 2, tg = lane & 3;

    int lrow = (lane & 7) + ((lane >> 3) & 1) * 8;
    int lk = (lane >> 4) * 4;
    uint32_t aLane = base + (uint32_t)(((wm * 32 + lrow) * 36 + lk) * 4);
    uint32_t bLane = base + (uint32_t)(((wn * 32 + lrow) * 36 + lk) * 4);

    const __half* wbase = whh + (size_t)dir * G4 * Hq;
    const __half* xgd = xg + (size_t)dir * Bq * Wq * G4;

    auto aStage = [&](int s) -> uint32_t { return (uint32_t)((R2_A0 + s * R2_ASZ) * 4); };
    auto bStage = [&](int s) -> uint32_t {
        return (uint32_t)((s == 2 ? R2_B2 : s * R2_BSZ) * 4);
    };

    // A source: habase + row * rstride  (set per step below)
    const __half* habase = nullptr;
    size_t rstride = LAYER0 ? (size_t)Wq * 2 * Hq : (size_t)Hq;

    auto load_A = [&](int s, int k0) {
        uint32_t ab = base + aStage(s);
#pragma unroll
        for (int i = 0; i < 2; i++) {
            int c = tid + i * 256;            // 64 rows x 8 segs
            int row = c >> 3, seg = c & 7;
            cp16(ab + (uint32_t)((row * 36 + seg * 4) * 4),
                 habase + (size_t)(m0 + row) * rstride + k0 + seg * 8);
        }
        asm volatile("cp.async.commit_group;");
    };
    auto load_Bw = [&](int s, int k0) {
        uint32_t bb = base + bStage(s);
#pragma unroll
        for (int i = 0; i < 4; i++) {
            int c = tid + i * 256;            // 128 rows x 8 segs
            int row = c >> 3, seg = c & 7;
            int grow = ((row >> 5) << 9) + ht0 + (row & 31);   // gate*512 + h
            cp16(bb + (uint32_t)((row * 36 + seg * 4) * 4),
                 wbase + (size_t)grow * Hq + k0 + seg * 8);
        }
        asm volatile("cp.async.commit_group;");
    };
    auto load_AB = [&](int s, int k0) {
        uint32_t ab = base + aStage(s);
        uint32_t bb = base + bStage(s);
#pragma unroll
        for (int i = 0; i < 2; i++) {
            int c = tid + i * 256;
            int row = c >> 3, seg = c & 7;
            cp16(ab + (uint32_t)((row * 36 + seg * 4) * 4),
                 habase + (size_t)(m0 + row) * rstride + k0 + seg * 8);
        }
#pragma unroll
        for (int i = 0; i < 4; i++) {
            int c = tid + i * 256;
            int row = c >> 3, seg = c & 7;
            int grow = ((row >> 5) << 9) + ht0 + (row & 31);
            cp16(bb + (uint32_t)((row * 36 + seg * 4) * 4),
                 wbase + (size_t)grow * Hq + k0 + seg * 8);
        }
        asm volatile("cp.async.commit_group;");
    };

    for (int step = 0; step < Wq; step++) {
        int t_ = dir ? (Wq - 1 - step) : step;

        // L2-prefetch this step's xg slice (64 rows x 4 gate segs)
        if (tid < 256) {
            int row = tid >> 2, seg = tid & 3;
            const __half* p = xgd + ((size_t)(m0 + row) * Wq + t_) * G4
                              + seg * 512 + ht0;
            asm volatile("prefetch.global.L2 [%0];" :: "l"(p));
        }

        float acc[2][4][4];
#pragma unroll
        for (int mt = 0; mt < 2; mt++)
#pragma unroll
            for (int nt = 0; nt < 4; nt++)
#pragma unroll
                for (int q = 0; q < 4; q++) acc[mt][nt][q] = 0.0f;

        if (step > 0) {
            if (LAYER0) {
                int tprev = dir ? (Wq - step) : (step - 1);
                habase = g_hseq_h + (size_t)tprev * 2 * Hq + dir * Hq;
            } else {
                habase = g_ha[(step - 1) & 1] + dir * Bq * Hq;
            }
            // B0,B1 already in flight (prefetched before the group barrier).
            load_A(0, 0);
            load_A(1, 64);

            for (int kc = 0; kc < 8; kc++) {       // BK = 64 halves, stage kc%3
                if (kc < 7) asm volatile("cp.async.wait_group 1;");
                else        asm volatile("cp.async.wait_group 0;");
                __syncthreads();
                if (kc == 0)      load_AB(2, 128);
                else if (kc <= 5) load_AB((kc + 2) % 3, (kc + 2) * 64);

                uint32_t sa = aStage(kc % 3);
                uint32_t sb = bStage(kc % 3);
#pragma unroll
                for (int g = 0; g < 4; g++) {
                    uint32_t kby = g * 32;
                    uint32_t af[2][4], bf[4][2];
#pragma unroll
                    for (int mt = 0; mt < 2; mt++)
                        LDSM_X4(af[mt][0], af[mt][1], af[mt][2], af[mt][3],
                                aLane + sa + (uint32_t)(mt * 16 * 36 * 4) + kby);
#pragma unroll
                    for (int p = 0; p < 2; p++)
                        LDSM_X4(bf[2 * p][0], bf[2 * p + 1][0], bf[2 * p][1], bf[2 * p + 1][1],
                                bLane + sb + (uint32_t)(p * 16 * 36 * 4) + kby);
#pragma unroll
                    for (int mt = 0; mt < 2; mt++)
#pragma unroll
                        for (int nt = 0; nt < 4; nt++) {
                            asm volatile(
                                "mma.sync.aligned.m16n8k16.row.col.f32.f16.f16.f32 "
                                "{%0,%1,%2,%3}, {%4,%5,%6,%7}, {%8,%9}, {%0,%1,%2,%3};"
                                : "+f"(acc[mt][nt][0]), "+f"(acc[mt][nt][1]),
                                  "+f"(acc[mt][nt][2]), "+f"(acc[mt][nt][3])
                                : "r"(af[mt][0]), "r"(af[mt][1]), "r"(af[mt][2]), "r"(af[mt][3]),
                                  "r"(bf[nt][0]), "r"(bf[nt][1]));
                        }
                }
            }
        }

        // all smem reads done; prefetch next step's weights into B0/B1 (disjoint
        // from the gsm alias region)
        __syncthreads();
        if (step < Wq - 1) {
            load_Bw(0, 0);
            load_Bw(1, 64);
        }

        // ---- stage gates into gsm (aliases A0..B2) ----
#pragma unroll
        for (int mt = 0; mt < 2; mt++)
#pragma unroll
            for (int nt = 0; nt < 4; nt++)
#pragma unroll
                for (int rs = 0; rs < 2; rs++) {
                    int mr = wm * 32 + mt * 16 + gid + rs * 8;
                    int nc = wn * 32 + nt * 8 + tg * 2;       // col = gate*32 + h
                    float2 v;
                    v.x = acc[mt][nt][rs * 2];
                    v.y = acc[mt][nt][rs * 2 + 1];
                    *(float2*)&gsm[mr * GSM_STRIDE + nc] = v;
                }
        __syncthreads();

        // ---- coalesced fused gate epilogue ----
        __half* haw = LAYER0 ? nullptr : (g_ha[step & 1] + dir * Bq * Hq);
        int hl = (tid & 15) * 2;
        int rb = tid >> 4;                 // 0..15
#pragma unroll
        for (int it = 0; it < 4; it++) {
            int m = it * 16 + rb;          // local row 0..63
            int gm = m0 + m;
            const float* gr = &gsm[m * GSM_STRIDE];
            const __half* xp = xgd + ((size_t)gm * Wq + t_) * G4 + ht0 + hl;
            float2 gi = *(const float2*)&gr[hl];
            float2 gf = *(const float2*)&gr[32 + hl];
            float2 gg = *(const float2*)&gr[64 + hl];
            float2 go = *(const float2*)&gr[96 + hl];
            float2 xi  = __half22float2(*(const __half2*)&xp[0]);
            float2 xf  = __half22float2(*(const __half2*)&xp[512]);
            float2 xgg = __half22float2(*(const __half2*)&xp[1024]);
            float2 xo  = __half22float2(*(const __half2*)&xp[1536]);
            int ci = dir * Bq * Hq + gm * Hq + ht0 + hl;
            float2 cprev = (step == 0) ? make_float2(0.f, 0.f) : *(const float2*)&g_c[ci];
            float2 cv, hv;
            cv.x = sig_fast(gf.x + xf.x) * cprev.x + sig_fast(gi.x + xi.x) * tanh_fast(gg.x + xgg.x);
            cv.y = sig_fast(gf.y + xf.y) * cprev.y + sig_fast(gi.y + xi.y) * tanh_fast(gg.y + xgg.y);
            hv.x = sig_fast(go.x + xo.x) * tanh_fast(cv.x);
            hv.y = sig_fast(go.y + xo.y) * tanh_fast(cv.y);
            *(float2*)&g_c[ci] = cv;
            __half2 hh = __floats2half2_rn(hv.x, hv.y);
            if (LAYER0) {
                size_t so = ((size_t)gm * Wq + t_) * (2 * Hq) + dir * Hq + ht0 + hl;
                *(__half2*)&g_hseq_h[so] = hh;
            } else {
                *(__half2*)&haw[gm * Hq + ht0 + hl] = hh;
                if (t_ == qlen[gm] - 1) {
                    *(float2*)&out[(size_t)gm * (2 * Hq) + dir * Hq + ht0 + hl] = hv;
                }
            }
        }

        // ---- group-local barrier (16 CTAs sharing (dir, m0)) ----
        if (step < Wq - 1) {
            __threadfence();
            __syncthreads();
            if (tid == 0) {
                unsigned* ctr = &g_gbar[bar_ofs + grp * Wq + step];
                atomicAdd(ctr, 1u);
                unsigned v;
                do {
                    asm volatile("ld.acquire.gpu.u32 %0, [%1];"
                                 : "=r"(v) : "l"(ctr) : "memory");
                    if (v < 16u) __nanosleep(32);
                } while (v < 16u);
            }
            __syncthreads();
        }
    }
}

// ---------------- launch ----------------
extern "C" void kernel_launch(void* const* d_in, const int* in_sizes, int n_in,
                              void* d_out, int out_size)
{
    const int*   ques = (const int*)d_in[0];
    const int*   qlen = (const int*)d_in[1];
    const float* lut  = (const float*)d_in[2];
    const float* wih0 = (const float*)d_in[3];
    const float* whh0 = (const float*)d_in[4];
    const float* b0   = (const float*)d_in[5];
    const float* wih1 = (const float*)d_in[6];
    const float* whh1 = (const float*)d_in[7];
    const float* b1   = (const float*)d_in[8];
    float* out = (float*)d_out;

    __half *table, *hseq_h, *wr, *xg;
    cudaGetSymbolAddress((void**)&table,  g_table);
    cudaGetSymbolAddress((void**)&xg,     g_xg);
    cudaGetSymbolAddress((void**)&hseq_h, g_hseq_h);
    cudaGetSymbolAddress((void**)&wr,     g_wr);

    cudaFuncSetAttribute(gemm_hf<1, 1>, cudaFuncAttributeMaxDynamicSharedMemorySize, P_SMEM);
    cudaFuncSetAttribute(gemm_hf<1, 0>, cudaFuncAttributeMaxDynamicSharedMemorySize, P_SMEM);
    cudaFuncSetAttribute(lstm_persist<0>, cudaFuncAttributeMaxDynamicSharedMemorySize, R2_SMEM);
    cudaFuncSetAttribute(lstm_persist<1>, cudaFuncAttributeMaxDynamicSharedMemorySize, R2_SMEM);

    // 0) fused: all weights -> half + barrier zeroing; table build
    cvt_all_weights_kernel<<<(W_TOTAL / 4 + 255) / 256, 256>>>(wih0, whh0, wih1, whh1);
    {
        dim3 grid((Vq + 31) / 32, Eq / 32);
        tanh_transpose_kernel<<<grid, dim3(32, 8)>>>(lut);
    }

    // 1) layer-0 input projection (embedding gather fused into A-load)
    {
        dim3 grid(G4 / 128, (Bq * Wq) / 128, 2);
        gemm_hf<1, 1><<<grid, 256, P_SMEM>>>(table, 0,
                                             wr + OFF_WIH0, (size_t)G4 * Eq,
                                             b0,
                                             xg, (size_t)Bq * Wq * G4,
                                             Bq * Wq, G4, Eq, ques);
    }

    // 2) layer-0 recurrence (h lives in hseq_h; no separate ping-pong)
    lstm_persist<1><<<R_NCTA, 256, R2_SMEM>>>(wr + OFF_WHH0, xg, qlen, out, 0);

    // 3) layer-1 input projection (K = 2H, A = half hseq)
    {
        dim3 grid(G4 / 128, (Bq * Wq) / 128, 2);
        gemm_hf<1, 0><<<grid, 256, P_SMEM>>>(hseq_h, 0,
                                             wr + OFF_WIH1, (size_t)G4 * 2 * Hq,
                                             b1,
                                             xg, (size_t)Bq * Wq * G4,
                                             Bq * Wq, G4, 2 * Hq, ques);
    }

    // 4) layer-1 recurrence (writes out directly at t = qlen-1; gather fused)
    lstm_persist<0><<<R_NCTA, 256, R2_SMEM>>>(wr + OFF_WHH1, xg, qlen, out, 32 * Wq);
}